// round 13
// baseline (speedup 1.0000x reference)
#include <cuda_runtime.h>
#include <cuda_fp16.h>
#include <stdint.h>

#define BB  4
#define AA  256
#define NN  64
#define NCB 128
#define NF  128
#define NSB 50

#define PITCH 136                         // fp16 image pitch (halves)
#define P8    144                         // int8 image pitch (bytes)
#define IMG_A16 (64 * PITCH * 2)          // 17408
#define IMG_A8  (64 * P8)                 // 9216
#define A8_L   17408u
#define VH_L   26624u
#define V8_L   44032u
#define ATOM_BLK 53248u                   // Ah + A8 + Vh + V8
#define IMG_W16 (128 * PITCH * 2)         // 34816
#define IMG_W8  (128 * P8)                // 18432
#define WBUF    53248u                    // Wh + W8
#define W0_OFF  106496u
#define W1_OFF  159744u
#define SMEM_BYTES 212992u
#define VPITCH  65
#define SA 2.0f
#define INIT_SMEM (4352 + 2*34816)        // 73984: Ah16 + Wh + Wl(fp16)

// ---------------- global scratch ----------------
__device__ __align__(16) float d_y[BB*AA*NF];
__device__ __align__(16) float d_vij[(size_t)BB*AA*NN*NCB];
__device__ __align__(16) float d_Vik[BB*AA*NCB*3];
__device__ __align__(16) char  d_wsplit[7 * 53248];   // per stage: Wh fp16 + W8 int8
__device__ float d_wInv[7];

// ---------------- helpers ----------------
__device__ __forceinline__ void cp16(void* sdst, const void* gsrc) {
    unsigned s = (unsigned)__cvta_generic_to_shared(sdst);
    asm volatile("cp.async.cg.shared.global [%0], [%1], 16;" :: "r"(s), "l"(gsrc));
}
__device__ __forceinline__ void ldsm4(uint32_t* r, uint32_t saddr) {
    asm volatile("ldmatrix.sync.aligned.m8n8.x4.shared.b16 {%0,%1,%2,%3}, [%4];"
        : "=r"(r[0]), "=r"(r[1]), "=r"(r[2]), "=r"(r[3]) : "r"(saddr));
}
__device__ __forceinline__ void mma16816(float* c, const uint32_t* a,
                                         uint32_t b0, uint32_t b1) {
    asm volatile("mma.sync.aligned.m16n8k16.row.col.f32.f16.f16.f32 "
        "{%0,%1,%2,%3}, {%4,%5,%6,%7}, {%8,%9}, {%0,%1,%2,%3};"
        : "+f"(c[0]), "+f"(c[1]), "+f"(c[2]), "+f"(c[3])
        : "r"(a[0]), "r"(a[1]), "r"(a[2]), "r"(a[3]), "r"(b0), "r"(b1));
}
__device__ __forceinline__ void mma16816h(uint32_t* c, const uint32_t* a,
                                          uint32_t b0, uint32_t b1) {
    asm volatile("mma.sync.aligned.m16n8k16.row.col.f16.f16.f16.f16 "
        "{%0,%1}, {%2,%3,%4,%5}, {%6,%7}, {%0,%1};"
        : "+r"(c[0]), "+r"(c[1])
        : "r"(a[0]), "r"(a[1]), "r"(a[2]), "r"(a[3]), "r"(b0), "r"(b1));
}
__device__ __forceinline__ void mma_s8(int* d, const uint32_t* a,
                                       uint32_t b0, uint32_t b1) {
    asm volatile("mma.sync.aligned.m16n8k32.row.col.s32.s8.s8.s32 "
        "{%0,%1,%2,%3}, {%4,%5,%6,%7}, {%8,%9}, {%0,%1,%2,%3};"
        : "+r"(d[0]), "+r"(d[1]), "+r"(d[2]), "+r"(d[3])
        : "r"(a[0]), "r"(a[1]), "r"(a[2]), "r"(a[3]), "r"(b0), "r"(b1));
}
__device__ __forceinline__ float sspf(float x) {
    if (x > 15.f) return x - 0.69314718055994531f;
    return __logf(1.f + __expf(x)) - 0.69314718055994531f;
}
__device__ __forceinline__ uint32_t smem_u32(const void* p) {
    return (uint32_t)__cvta_generic_to_shared(p);
}
__device__ __forceinline__ int q8(float x) {
    int q = __float2int_rn(x * SA);
    return max(-127, min(127, q));
}
__device__ __forceinline__ void mbar_wait(uint32_t mb, uint32_t parity) {
    uint32_t done;
    asm volatile("{\n\t.reg .pred p;\n\t"
        "mbarrier.try_wait.parity.acquire.cta.shared::cta.b64 p, [%1], %2;\n\t"
        "selp.b32 %0, 1, 0, p;\n\t}"
        : "=r"(done) : "r"(mb), "r"(parity) : "memory");
    if (!done) {
        asm volatile("{\n\t.reg .pred P1;\n\t"
            "W_%=:\n\t"
            "mbarrier.try_wait.parity.acquire.cta.shared::cta.b64 P1, [%0], %1, 0x989680;\n\t"
            "@P1 bra.uni D_%=;\n\t"
            "bra.uni W_%=;\n\t"
            "D_%=:\n\t}"
            :: "r"(mb), "r"(parity) : "memory");
    }
}

// ---------------- kernel: weight prep (0-6) + HMMA embed (7-70) ------------
__global__ void __launch_bounds__(128) k_init(
    const float* fW1, const float* fW2, const float* f2oW,
    const float* pW1, const float* pW2, const float* eW1, const float* eW2,
    const float* __restrict__ xi, const float* __restrict__ in2f_W) {
    extern __shared__ char sdyn[];
    int bid = blockIdx.x;
    int tid = threadIdx.x;
    if (bid < 7) {
        const float* W; int K, realK;
        switch (bid) {
            case 0: W = fW1;  K = 64;  realK = NSB; break;
            case 1: W = fW2;  K = 128; realK = 128; break;
            case 2: W = f2oW; K = 128; realK = 128; break;
            case 3: W = pW1;  K = 128; realK = 128; break;
            case 4: W = pW2;  K = 128; realK = 128; break;
            case 5: W = eW1;  K = 128; realK = 128; break;
            default: W = eW2; K = 128; realK = 128; break;
        }
        __half* hi = reinterpret_cast<__half*>(d_wsplit + (size_t)bid * 53248);
        char*  w8 = d_wsplit + (size_t)bid * 53248 + IMG_W16;
        __shared__ float red[128];
        float mx = 0.f;
        for (int i = tid; i < 128 * K; i += 128) {
            int n = i / K, k = i - (i / K) * K;
            float v = (k < realK) ? W[k * 128 + n] : 0.f;   // B^T: [n][k]
            __half h = __float2half_rn(v);
            hi[n * PITCH + k] = h;
            float l = fabsf(v - __half2float(h));
            if (l > mx) mx = l;
        }
        red[tid] = mx;
        __syncthreads();
        #pragma unroll
        for (int off = 64; off > 0; off >>= 1) {
            if (tid < off) red[tid] = fmaxf(red[tid], red[tid + off]);
            __syncthreads();
        }
        float m = red[0];
        float SW = (m > 1e-30f) ? (127.f / m) : 1.f;
        if (tid == 0) d_wInv[bid] = 1.f / (SA * SW);
        for (int i = tid; i < 128 * K; i += 128) {
            int n = i / K, k = i - (i / K) * K;
            float v = (k < realK) ? W[k * 128 + n] : 0.f;
            float l = v - __half2float(__float2half_rn(v));
            int q = __float2int_rn(l * SW);
            w8[n * P8 + k] = (char)max(-127, min(127, q));
        }
    } else {
        // HMMA embed: 16 rows per block (64 blocks)
        const int row0 = (bid - 7) * 16;
        __half* Ah = reinterpret_cast<__half*>(sdyn);            // 16 x PITCH
        __half* Wh = reinterpret_cast<__half*>(sdyn + 4352);
        __half* Wl = reinterpret_cast<__half*>(sdyn + 4352 + 34816);
        for (int i = tid; i < 16 * 128; i += 128) {
            int r = i >> 7, c = i & 127;
            Ah[r * PITCH + c] = __float2half_rn(xi[(size_t)(row0 + r) * 128 + c]);
        }
        for (int i = tid; i < 128 * 128; i += 128) {
            int k = i >> 7, n = i & 127;
            float v = __ldg(in2f_W + i);
            __half h = __float2half_rn(v);
            Wh[n * PITCH + k] = h;
            Wl[n * PITCH + k] = __float2half_rn(v - __half2float(h));
        }
        __syncthreads();

        const int lw = tid >> 5, lane = tid & 31;
        const int n0 = lw * 32;
        const int rsel = lane & 15, hsel = lane >> 4;
        uint32_t aA = smem_u32(Ah) + (uint32_t)((rsel * PITCH + hsel*8) * 2);
        uint32_t wA = smem_u32(Wh) + (uint32_t)(((n0 + rsel) * PITCH + hsel*8) * 2);
        const uint32_t STEP16 = 16 * PITCH * 2;
        float acc[4][4];
        uint32_t accL[4][2];
        #pragma unroll
        for (int g = 0; g < 4; g++) {
            #pragma unroll
            for (int j = 0; j < 4; j++) acc[g][j] = 0.f;
            accL[g][0] = 0u; accL[g][1] = 0u;
        }
        #pragma unroll 2
        for (int kk = 0; kk < 8; kk++) {
            uint32_t A[4], W0[4], W1[4], L0[4], L1[4];
            uint32_t ko = kk * 32;
            ldsm4(A,  aA + ko);
            ldsm4(W0, wA + ko);
            ldsm4(W1, wA + ko + STEP16);
            ldsm4(L0, wA + ko + 34816);
            ldsm4(L1, wA + ko + 34816 + STEP16);
            mma16816(acc[0], A, W0[0], W0[2]);  mma16816h(accL[0], A, L0[0], L0[2]);
            mma16816(acc[1], A, W0[1], W0[3]);  mma16816h(accL[1], A, L0[1], L0[3]);
            mma16816(acc[2], A, W1[0], W1[2]);  mma16816h(accL[2], A, L1[0], L1[2]);
            mma16816(acc[3], A, W1[1], W1[3]);  mma16816h(accL[3], A, L1[1], L1[3]);
        }
        const int er = lane >> 2, ec2 = (lane & 3) * 2;
        #pragma unroll
        for (int g = 0; g < 4; g++) {
            int col = n0 + g*8 + ec2;
            #pragma unroll
            for (int h = 0; h < 2; h++) {
                int row = er + h*8;
                __half2 lo2 = *reinterpret_cast<__half2*>(&accL[g][h]);
                float x0 = acc[g][h*2+0] + __half2float(lo2.x);
                float x1 = acc[g][h*2+1] + __half2float(lo2.y);
                *reinterpret_cast<float2*>(
                    d_y + (size_t)(row0 + row) * 128 + col) = make_float2(x0, x1);
            }
        }
    }
}

// mixed GEMM: fp16 hi product + int8 k32 correction, m32n32 warp tile
template<int CHUNKS>
__device__ __forceinline__ void mm(uint32_t a16, uint32_t a8,
                                   uint32_t w16, uint32_t w8,
                                   float (&acc)[8][4], int lw, int lane,
                                   float inv) {
    const int warp_m = (lw >> 2) & 1, warp_n = lw & 3;
    const int rsel = lane & 15, hsel = lane >> 4;
    uint32_t a16A = a16 + (uint32_t)(((warp_m*32 + rsel) * PITCH + hsel*8) * 2);
    uint32_t w16A = w16 + (uint32_t)(((warp_n*32 + rsel) * PITCH + hsel*8) * 2);
    const uint32_t STEP16 = 16 * PITCH * 2;
    const int rA8 = warp_m*32 + ((lane>>3)&1)*8 + (lane&7);
    const int kA8 = (lane>>4)*16;
    uint32_t a8A0 = a8 + (uint32_t)(rA8 * P8 + kA8);
    uint32_t a8A1 = a8A0 + 16 * P8;
    const int rW8 = warp_n*32 + ((lane>>4)<<3) + (lane&7);
    const int kW8 = ((lane>>3)&1)*16;
    uint32_t w8A0 = w8 + (uint32_t)(rW8 * P8 + kW8);
    uint32_t w8A1 = w8A0 + 16 * P8;

    #pragma unroll
    for (int c = 0; c < CHUNKS; c++) {
        // hi product: 2 fp16 ksteps
        #pragma unroll
        for (int kk = 0; kk < 2; kk++) {
            uint32_t A0[4], A1[4], W0[4], W1[4];
            uint32_t ko = (uint32_t)(c*2 + kk) * 32;
            ldsm4(A0, a16A + ko);
            ldsm4(A1, a16A + ko + STEP16);
            ldsm4(W0, w16A + ko);
            ldsm4(W1, w16A + ko + STEP16);
            mma16816(acc[0], A0, W0[0], W0[2]);
            mma16816(acc[1], A0, W0[1], W0[3]);
            mma16816(acc[2], A0, W1[0], W1[2]);
            mma16816(acc[3], A0, W1[1], W1[3]);
            mma16816(acc[4], A1, W0[0], W0[2]);
            mma16816(acc[5], A1, W0[1], W0[3]);
            mma16816(acc[6], A1, W1[0], W1[2]);
            mma16816(acc[7], A1, W1[1], W1[3]);
        }
        // correction: int8 k32, folded immediately
        {
            uint32_t A8f[2][4], W8f[2][4];
            uint32_t ko = (uint32_t)c * 32;
            ldsm4(A8f[0], a8A0 + ko);
            ldsm4(A8f[1], a8A1 + ko);
            ldsm4(W8f[0], w8A0 + ko);
            ldsm4(W8f[1], w8A1 + ko);
            #pragma unroll
            for (int mt = 0; mt < 2; mt++)
                #pragma unroll
                for (int g = 0; g < 4; g++) {
                    int t = mt*4 + g;
                    int d[4] = {0, 0, 0, 0};
                    mma_s8(d, A8f[mt], W8f[g>>1][(g&1)*2], W8f[g>>1][(g&1)*2+1]);
                    acc[t][0] += (float)d[0] * inv;
                    acc[t][1] += (float)d[1] * inv;
                    acc[t][2] += (float)d[2] * inv;
                    acc[t][3] += (float)d[3] * inv;
                }
        }
    }
}

// stage epilogue for one pipeline
__device__ __forceinline__ void epilogue(
    int s, float (&acc)[8][4], char* smem, int pid, int ba0,
    int lw, int lane, const float (*sBias)[128],
    const float* sCut, const int* sNbr)
{
    const int warp_m = (lw >> 2) & 1, warp_n = lw & 3;
    const int er = lane >> 2, ec2 = (lane & 3) * 2;
    char* atomBase = smem + pid * ATOM_BLK;
    char* dstH = atomBase + ((s == 2) ? VH_L : 0u);
    char* dst8 = atomBase + ((s == 2) ? V8_L : A8_L);
    float* vikT = reinterpret_cast<float*>(smem + W0_OFF + pid * 33280u);
    const int baG = ba0 + pid;
    const int bA = baG >> 8;
    #pragma unroll
    for (int mt = 0; mt < 2; mt++) {
        #pragma unroll
        for (int nt = 0; nt < 4; nt++) {
            int t = mt*4 + nt;
            int col = warp_n*32 + nt*8 + ec2;
            float b0 = sBias[s][col], b1 = sBias[s][col + 1];
            #pragma unroll
            for (int h = 0; h < 2; h++) {
                int row = warp_m*32 + mt*16 + er + h*8;   // 0..63
                int grow = pid*64 + row;
                float x0 = acc[t][h*2+0] + b0;
                float x1 = acc[t][h*2+1] + b1;
                if (s == 1) {
                    float cu = sCut[grow];
                    const float2 y = *reinterpret_cast<const float2*>(
                        d_y + ((size_t)((bA << 8) + sNbr[grow]) << 7) + col);
                    x0 = x0 * cu * y.x;
                    x1 = x1 * cu * y.y;
                } else if (s == 4) {
                    *reinterpret_cast<float2*>(
                        d_vij + ((size_t)baG * 64 + row) * 128 + col) =
                        make_float2(x0, x1);
                    continue;
                } else if (s == 6) {
                    vikT[col * VPITCH + row]       = x0;
                    vikT[(col + 1) * VPITCH + row] = x1;
                    continue;
                } else {
                    x0 = sspf(x0); x1 = sspf(x1);
                }
                __half2 hp = __floats2half2_rn(x0, x1);
                uint32_t off = (uint32_t)(row * PITCH + col) * 2;
                *reinterpret_cast<uint32_t*>(dstH + off) = *reinterpret_cast<uint32_t*>(&hp);
                *reinterpret_cast<char2*>(dst8 + row * P8 + col) =
                    make_char2((char)q8(x0), (char)q8(x1));
            }
        }
    }
}

// ---------------- kernel: fused interaction, double-buffered W -------------
__global__ void __launch_bounds__(512, 1) k_main(
    const float* __restrict__ r_ij, const float* __restrict__ cos_ij,
    const float* __restrict__ f_ij, const float* __restrict__ nmask,
    const float* __restrict__ fb1, const float* __restrict__ fb2,
    const float* __restrict__ f2ob,
    const float* __restrict__ aW1, const float* __restrict__ ab1,
    const float* __restrict__ aW2, const float* __restrict__ ab2,
    const float* __restrict__ pb1, const float* __restrict__ pb2,
    const float* __restrict__ eb1, const float* __restrict__ eb2,
    const int* __restrict__ neighbors, float* __restrict__ out_vi)
{
    extern __shared__ char smem[];
    const uint32_t sb = smem_u32(smem);
    const int tid = threadIdx.x;
    const int pid = tid >> 8;
    const int lt  = tid & 255, lw = lt >> 5, lane = tid & 31;
    const int ba0 = blockIdx.x * 2;

    __shared__ float sCut[128], sMask[128], cmS[384], vsumS[256], hidS[256];
    __shared__ float sBias[7][128];
    __shared__ int   sNbr[128];
    __shared__ __align__(8) uint64_t mbarW[2];
    const uint32_t mbar0 = smem_u32(&mbarW[0]);
    const uint32_t mbar1 = smem_u32(&mbarW[1]);

    if (tid == 0) {
        asm volatile("mbarrier.init.shared.b64 [%0], %1;" :: "r"(mbar0), "r"(512u) : "memory");
        asm volatile("mbarrier.init.shared.b64 [%0], %1;" :: "r"(mbar1), "r"(512u) : "memory");
    }

    {   // biases to smem
        const float* bp[7] = {fb1, fb2, f2ob, pb1, pb2, eb1, eb2};
        for (int i = tid; i < 7*128; i += 512)
            sBias[i >> 7][i & 127] = __ldg(bp[i >> 7] + (i & 127));
    }
    if (tid < 128) {
        int g = ba0 * NN + tid;
        float r = r_ij[g];
        sCut[tid]  = (r < 5.f) ? 0.5f * (__cosf(r * 0.62831853071795864f) + 1.f) : 0.f;
        float m = nmask[g];
        sMask[tid] = m;
        sNbr[tid]  = neighbors[g];
        cmS[tid*3+0] = cos_ij[(size_t)g*3+0] * m;
        cmS[tid*3+1] = cos_ij[(size_t)g*3+1] * m;
        cmS[tid*3+2] = cos_ij[(size_t)g*3+2] * m;
    }
    {   // zero both atom blocks (fp16 + int8 images)
        uint64_t* z = reinterpret_cast<uint64_t*>(smem);
        for (int i = tid; i < (int)(2*ATOM_BLK)/8; i += 512) z[i] = 0ull;
    }
    __syncthreads();

    {   // issue W(0) -> buf0
        const char* src = d_wsplit;
        for (int i = tid * 16; i < (int)WBUF; i += 512*16)
            cp16(smem + W0_OFF + i, src + i);
        asm volatile("cp.async.mbarrier.arrive.noinc.shared.b64 [%0];"
                     :: "r"(mbar0) : "memory");
    }
    {   // scatter features: fp16 + int8 images
        const float* fg = f_ij + (size_t)(ba0 + pid) * NN * NSB;
        char* ab = smem + pid * ATOM_BLK;
        __half* ah = reinterpret_cast<__half*>(ab);
        char*  a8 = ab + A8_L;
        for (int i = lt; i < NN * NSB; i += 256) {
            int r = i / NSB, c = i - (i / NSB) * NSB;
            float v = fg[i];
            ah[r * PITCH + c] = __float2half_rn(v);
            a8[r * P8 + c]    = (char)q8(v);
        }
    }
    __syncthreads();

    float acc[8][4];

    for (int s = 0; s < 7; s++) {
        if (s < 6) {   // issue W(s+1) — full stage of lead
            const char* src = d_wsplit + (size_t)(s + 1) * 53248;
            uint32_t woff = ((s + 1) & 1) ? W1_OFF : W0_OFF;
            for (int i = tid * 16; i < (int)WBUF; i += 512*16)
                cp16(smem + woff + i, src + i);
            asm volatile("cp.async.mbarrier.arrive.noinc.shared.b64 [%0];"
                         :: "r"(((s + 1) & 1) ? mbar1 : mbar0) : "memory");
        }

        // Q: epilogue of previous stage overlaps P's MMAs
        if (pid == 1 && s > 0) {
            epilogue(s - 1, acc, smem, 1, ba0, lw, lane, sBias, sCut, sNbr);
            asm volatile("bar.sync 2, 256;" ::: "memory");
        }
        #pragma unroll
        for (int t = 0; t < 8; t++)
            #pragma unroll
            for (int j = 0; j < 4; j++) acc[t][j] = 0.f;

        mbar_wait((s & 1) ? mbar1 : mbar0, (uint32_t)((s >> 1) & 1));

        const bool useV = (s == 3 || s == 5);
        uint32_t a16 = sb + pid * ATOM_BLK + (useV ? VH_L : 0u);
        uint32_t a8  = sb + pid * ATOM_BLK + (useV ? V8_L : A8_L);
        uint32_t w16 = sb + ((s & 1) ? W1_OFF : W0_OFF);
        uint32_t w8  = w16 + IMG_W16;
        float inv = __ldg(d_wInv + s);
        if (s == 0) mm<2>(a16, a8, w16, w8, acc, lw, lane, inv);
        else        mm<4>(a16, a8, w16, w8, acc, lw, lane, inv);

        if (pid == 0 && s < 6)
            epilogue(s, acc, smem, 0, ba0, lw, lane, sBias, sCut, sNbr);

        __syncthreads();
    }

    // stage-6 epilogues (both pipelines) -> vikT (W buffers now free)
    epilogue(6, acc, smem, pid, ba0, lw, lane, sBias, sCut, sNbr);
    __syncthreads();

    // ---- Vik[c][d] = sum_n vik[n][c] * cm[n][d] ----
    for (int e = tid; e < 768; e += 512) {
        int atom = e / 384, rem = e - atom * 384;
        int c = rem / 3, d = rem - 3 * (rem / 3);
        const float* vikT = reinterpret_cast<const float*>(smem + W0_OFF + atom * 33280u);
        float s = 0.f;
        #pragma unroll 4
        for (int n = 0; n < 64; n++)
            s = fmaf(vikT[c * VPITCH + n], cmS[(atom*64 + n) * 3 + d], s);
        d_Vik[(size_t)(ba0 + atom) * 384 + rem] = s;
    }

    // ---- vsum from V (fp16 image), atom MLP -> out_vi ----
    if (tid < 256) {
        int atom = tid >> 7, c = tid & 127;
        const __half* vh = reinterpret_cast<const __half*>(smem + atom*ATOM_BLK + VH_L);
        float s = 0.f;
        #pragma unroll 4
        for (int n = 0; n < 64; n++)
            s = fmaf(__half2float(vh[n * PITCH + c]), sMask[atom*64 + n], s);
        vsumS[tid] = s;
    }
    __syncthreads();
    if (tid < 256) {
        int atom = tid >> 7, c = tid & 127;
        float h = __ldg(ab1 + c);
        #pragma unroll 4
        for (int k = 0; k < 128; k++)
            h = fmaf(vsumS[atom*128 + k], __ldg(aW1 + k * 128 + c), h);
        hidS[tid] = sspf(h);
    }
    __syncthreads();
    if (tid < 256) {
        int atom = tid >> 7, c = tid & 127;
        float o = __ldg(ab2 + c);
        #pragma unroll 4
        for (int k = 0; k < 128; k++)
            o = fmaf(hidS[atom*128 + k], __ldg(aW2 + k * 128 + c), o);
        out_vi[(size_t)(ba0 + atom) * NF + c] = o;
    }
}

// ---------------- kernel: assemble V (warp per idx, 12 floats/lane) --------
__global__ void __launch_bounds__(256) k_assemble(
    const float* __restrict__ cos_ij,
    const int* __restrict__ neighbors,
    float* __restrict__ outV) {
    int idx  = blockIdx.x * 8 + (threadIdx.x >> 5);
    int lane = threadIdx.x & 31;
    int ba   = idx >> 6;
    int b    = idx >> 14;
    int nb   = __ldg(neighbors + idx);
    int e0   = lane * 12;

    const float* vikL = d_Vik + (size_t)ba * 384 + e0;
    const float* vikN = d_Vik + ((size_t)(b * AA + nb)) * 384 + e0;
    float4 l0 = *reinterpret_cast<const float4*>(vikL);
    float4 l1 = *reinterpret_cast<const float4*>(vikL + 4);
    float4 l2 = *reinterpret_cast<const float4*>(vikL + 8);
    float4 n0 = *reinterpret_cast<const float4*>(vikN);
    float4 n1 = *reinterpret_cast<const float4*>(vikN + 4);
    float4 n2 = *reinterpret_cast<const float4*>(vikN + 8);
    float4 vij4 = __ldg(reinterpret_cast<const float4*>(d_vij + (size_t)idx * 128) + lane);
    float cc0 = __ldg(cos_ij + (size_t)idx * 3 + 0);
    float cc1 = __ldg(cos_ij + (size_t)idx * 3 + 1);
    float cc2 = __ldg(cos_ij + (size_t)idx * 3 + 2);

    float vs[12] = {l0.x+n0.x, l0.y+n0.y, l0.z+n0.z, l0.w+n0.w,
                    l1.x+n1.x, l1.y+n1.y, l1.z+n1.z, l1.w+n1.w,
                    l2.x+n2.x, l2.y+n2.y, l2.z+n2.z, l2.w+n2.w};
    float vij[4] = {vij4.x, vij4.y, vij4.z, vij4.w};
    float cc[3]  = {cc0, cc1, cc2};
    float o[12];
    #pragma unroll
    for (int j = 0; j < 12; j++) {
        int c = j / 3, d = j - 3 * c;
        o[j] = fmaf(vij[c], cc[d], vs[j]);
    }
    float* dst = outV + (size_t)idx * 384 + e0;
    *reinterpret_cast<float4*>(dst)     = make_float4(o[0], o[1], o[2],  o[3]);
    *reinterpret_cast<float4*>(dst + 4) = make_float4(o[4], o[5], o[6],  o[7]);
    *reinterpret_cast<float4*>(dst + 8) = make_float4(o[8], o[9], o[10], o[11]);
}

// ---------------- launch ----------------
extern "C" void kernel_launch(void* const* d_in, const int* in_sizes, int n_in,
                              void* d_out, int out_size) {
    const float* xi       = (const float*)d_in[0];
    const float* r_ij     = (const float*)d_in[1];
    const float* cos_ij   = (const float*)d_in[2];
    const float* f_ij     = (const float*)d_in[3];
    const float* nmask    = (const float*)d_in[4];
    const float* fW1      = (const float*)d_in[5];
    const float* fb1      = (const float*)d_in[6];
    const float* fW2      = (const float*)d_in[7];
    const float* fb2      = (const float*)d_in[8];
    const float* in2f_W   = (const float*)d_in[9];
    const float* f2oW     = (const float*)d_in[10];
    const float* f2ob     = (const float*)d_in[11];
    const float* aW1      = (const float*)d_in[12];
    const float* ab1      = (const float*)d_in[13];
    const float* aW2      = (const float*)d_in[14];
    const float* ab2      = (const float*)d_in[15];
    const float* pW1      = (const float*)d_in[16];
    const float* pb1      = (const float*)d_in[17];
    const float* pW2      = (const float*)d_in[18];
    const float* pb2      = (const float*)d_in[19];
    const float* eW1      = (const float*)d_in[20];
    const float* eb1      = (const float*)d_in[21];
    const float* eW2      = (const float*)d_in[22];
    const float* eb2      = (const float*)d_in[23];
    const int*   neighbors= (const int*)d_in[24];

    float* out = (float*)d_out;
    float* out_vi = out;                          // [B,A,NCB]
    float* out_V  = out + (size_t)BB*AA*NCB;      // [B,A,N,NCB,3]

    cudaFuncSetAttribute(k_init, cudaFuncAttributeMaxDynamicSharedMemorySize,
                         (int)INIT_SMEM);
    cudaFuncSetAttribute(k_main, cudaFuncAttributeMaxDynamicSharedMemorySize,
                         (int)SMEM_BYTES);

    k_init<<<7 + BB*AA/16, 128, INIT_SMEM>>>(fW1, fW2, f2oW, pW1, pW2, eW1, eW2,
                                             xi, in2f_W);
    k_main<<<BB*AA/2, 512, SMEM_BYTES>>>(
        r_ij, cos_ij, f_ij, nmask,
        fb1, fb2, f2ob, aW1, ab1, aW2, ab2,
        pb1, pb2, eb1, eb2, neighbors, out_vi);
    k_assemble<<<BB*AA*NN/8, 256>>>(cos_ij, neighbors, out_V);
}

// round 14
// speedup vs baseline: 1.1277x; 1.1277x over previous
#include <cuda_runtime.h>
#include <cuda_fp16.h>
#include <stdint.h>

#define BB  4
#define AA  256
#define NN  64
#define NCB 128
#define NF  128
#define NSB 50

#define PITCH 136
#define IMG_A (64 * PITCH * 2)          // 17408
#define IMG_W (128 * PITCH * 2)         // 34816
#define WBUF  (2 * IMG_W)               // 69632 (hi + lo)
#define AH_OFF 0u
#define VH_OFF 17408u
#define W0_OFF 34816u
#define W1_OFF 104448u
#define VIK_OFF 174080u
#define SMEM_BYTES 207360u              // VIK_OFF + 128*65*4
#define VPITCH 65
#define INIT_SMEM (IMG_A + 2 * IMG_W)   // 87040
#define NUNITS (BB*AA)                  // 1024 atoms
#define NCTA 148

// ---------------- global scratch ----------------
__device__ __align__(16) float d_y[BB*AA*NF];
__device__ __align__(16) float d_vij[(size_t)BB*AA*NN*NCB];
__device__ __align__(16) float d_Vik[BB*AA*NCB*3];
__device__ __align__(16) __half d_wsplit[7 * 2 * 128 * PITCH];

// ---------------- helpers ----------------
__device__ __forceinline__ void cp16(void* sdst, const void* gsrc) {
    unsigned s = (unsigned)__cvta_generic_to_shared(sdst);
    asm volatile("cp.async.cg.shared.global [%0], [%1], 16;" :: "r"(s), "l"(gsrc));
}
__device__ __forceinline__ void ldsm4(uint32_t* r, uint32_t saddr) {
    asm volatile("ldmatrix.sync.aligned.m8n8.x4.shared.b16 {%0,%1,%2,%3}, [%4];"
        : "=r"(r[0]), "=r"(r[1]), "=r"(r[2]), "=r"(r[3]) : "r"(saddr));
}
__device__ __forceinline__ void mma16816(float* c, const uint32_t* a,
                                         uint32_t b0, uint32_t b1) {
    asm volatile("mma.sync.aligned.m16n8k16.row.col.f32.f16.f16.f32 "
        "{%0,%1,%2,%3}, {%4,%5,%6,%7}, {%8,%9}, {%0,%1,%2,%3};"
        : "+f"(c[0]), "+f"(c[1]), "+f"(c[2]), "+f"(c[3])
        : "r"(a[0]), "r"(a[1]), "r"(a[2]), "r"(a[3]), "r"(b0), "r"(b1));
}
__device__ __forceinline__ void mma16816h(uint32_t* c, const uint32_t* a,
                                          uint32_t b0, uint32_t b1) {
    asm volatile("mma.sync.aligned.m16n8k16.row.col.f16.f16.f16.f16 "
        "{%0,%1}, {%2,%3,%4,%5}, {%6,%7}, {%0,%1};"
        : "+r"(c[0]), "+r"(c[1])
        : "r"(a[0]), "r"(a[1]), "r"(a[2]), "r"(a[3]), "r"(b0), "r"(b1));
}
__device__ __forceinline__ float sspf(float x) {
    if (x > 15.f) return x - 0.69314718055994531f;
    return __logf(1.f + __expf(x)) - 0.69314718055994531f;
}
__device__ __forceinline__ uint32_t smem_u32(const void* p) {
    return (uint32_t)__cvta_generic_to_shared(p);
}
__device__ __forceinline__ void mbar_wait(uint32_t mb, uint32_t parity) {
    uint32_t done;
    asm volatile("{\n\t.reg .pred p;\n\t"
        "mbarrier.try_wait.parity.acquire.cta.shared::cta.b64 p, [%1], %2;\n\t"
        "selp.b32 %0, 1, 0, p;\n\t}"
        : "=r"(done) : "r"(mb), "r"(parity) : "memory");
    if (!done) {
        asm volatile("{\n\t.reg .pred P1;\n\t"
            "W_%=:\n\t"
            "mbarrier.try_wait.parity.acquire.cta.shared::cta.b64 P1, [%0], %1, 0x989680;\n\t"
            "@P1 bra.uni D_%=;\n\t"
            "bra.uni W_%=;\n\t"
            "D_%=:\n\t}"
            :: "r"(mb), "r"(parity) : "memory");
    }
}

// ---------------- kernel: weight prep (blocks 0-6) + HMMA embed (7-22) -----
__global__ void __launch_bounds__(256) k_init(
    const float* fW1, const float* fW2, const float* f2oW,
    const float* pW1, const float* pW2, const float* eW1, const float* eW2,
    const float* __restrict__ xi, const float* __restrict__ in2f_W) {
    extern __shared__ char sdyn[];
    int bid = blockIdx.x;
    int tid = threadIdx.x;
    if (bid < 7) {
        const float* W; int K, realK;
        switch (bid) {
            case 0: W = fW1;  K = 64;  realK = NSB; break;
            case 1: W = fW2;  K = 128; realK = 128; break;
            case 2: W = f2oW; K = 128; realK = 128; break;
            case 3: W = pW1;  K = 128; realK = 128; break;
            case 4: W = pW2;  K = 128; realK = 128; break;
            case 5: W = eW1;  K = 128; realK = 128; break;
            default: W = eW2; K = 128; realK = 128; break;
        }
        __half* hi = d_wsplit + (size_t)bid * 2 * 128 * PITCH;
        __half* lo = hi + 128 * PITCH;
        for (int i = tid; i < 128 * K; i += 256) {
            int n = i / K, k = i - (i / K) * K;
            float v = (k < realK) ? W[k * 128 + n] : 0.f;   // B^T: [n][k]
            __half h = __float2half_rn(v);
            hi[n * PITCH + k] = h;
            lo[n * PITCH + k] = __float2half_rn(v - __half2float(h));
        }
    } else {
        // HMMA embed: 64 rows per block; d_y = xi @ in2f_W (fp16 2-product)
        const int row0 = (bid - 7) * 64;
        __half* Ah = reinterpret_cast<__half*>(sdyn);
        __half* Wh = reinterpret_cast<__half*>(sdyn + IMG_A);
        __half* Wl = Wh + 128 * PITCH;
        for (int i = tid; i < 64 * 128; i += 256) {
            int r = i >> 7, c = i & 127;
            Ah[r * PITCH + c] = __float2half_rn(xi[(size_t)(row0 + r) * 128 + c]);
        }
        for (int i = tid; i < 128 * 128; i += 256) {
            int k = i >> 7, n = i & 127;
            float v = __ldg(in2f_W + i);
            __half h = __float2half_rn(v);
            Wh[n * PITCH + k] = h;
            Wl[n * PITCH + k] = __float2half_rn(v - __half2float(h));
        }
        __syncthreads();

        float acc[8][4];
        uint32_t accL[8][2];
        #pragma unroll
        for (int t = 0; t < 8; t++) {
            #pragma unroll
            for (int j = 0; j < 4; j++) acc[t][j] = 0.f;
            accL[t][0] = 0u; accL[t][1] = 0u;
        }
        const int lw = tid >> 5, lane = tid & 31;
        const int warp_m = (lw >> 2) & 1, warp_n = lw & 3;
        const int rsel = lane & 15, hsel = lane >> 4;
        uint32_t aA = smem_u32(Ah) + (uint32_t)(((warp_m*32 + rsel) * PITCH + hsel*8) * 2);
        uint32_t wA = smem_u32(Wh) + (uint32_t)(((warp_n*32 + rsel) * PITCH + hsel*8) * 2);
        const uint32_t STEP16 = 16 * PITCH * 2;
        #pragma unroll 2
        for (int kk = 0; kk < 8; kk++) {
            uint32_t A0[4], A1[4], W0[4], W1[4], L0[4], L1[4];
            uint32_t ko = kk * 32;
            ldsm4(A0, aA + ko);
            ldsm4(A1, aA + ko + STEP16);
            ldsm4(W0, wA + ko);
            ldsm4(W1, wA + ko + STEP16);
            ldsm4(L0, wA + ko + IMG_W);
            ldsm4(L1, wA + ko + IMG_W + STEP16);
            mma16816(acc[0], A0, W0[0], W0[2]);  mma16816h(accL[0], A0, L0[0], L0[2]);
            mma16816(acc[1], A0, W0[1], W0[3]);  mma16816h(accL[1], A0, L0[1], L0[3]);
            mma16816(acc[2], A0, W1[0], W1[2]);  mma16816h(accL[2], A0, L1[0], L1[2]);
            mma16816(acc[3], A0, W1[1], W1[3]);  mma16816h(accL[3], A0, L1[1], L1[3]);
            mma16816(acc[4], A1, W0[0], W0[2]);  mma16816h(accL[4], A1, L0[0], L0[2]);
            mma16816(acc[5], A1, W0[1], W0[3]);  mma16816h(accL[5], A1, L0[1], L0[3]);
            mma16816(acc[6], A1, W1[0], W1[2]);  mma16816h(accL[6], A1, L1[0], L1[2]);
            mma16816(acc[7], A1, W1[1], W1[3]);  mma16816h(accL[7], A1, L1[1], L1[3]);
        }
        const int er = lane >> 2, ec2 = (lane & 3) * 2;
        #pragma unroll
        for (int mt = 0; mt < 2; mt++)
            #pragma unroll
            for (int nt = 0; nt < 4; nt++) {
                int t = mt*4 + nt;
                int col = warp_n*32 + nt*8 + ec2;
                #pragma unroll
                for (int h = 0; h < 2; h++) {
                    int row = warp_m*32 + mt*16 + er + h*8;
                    __half2 lo2 = *reinterpret_cast<__half2*>(&accL[t][h]);
                    float x0 = acc[t][h*2+0] + __half2float(lo2.x);
                    float x1 = acc[t][h*2+1] + __half2float(lo2.y);
                    *reinterpret_cast<float2*>(
                        d_y + (size_t)(row0 + row) * 128 + col) = make_float2(x0, x1);
                }
            }
    }
}

// 2-product GEMM, m16n32 warp tile (16 warps cover 64x128), pipelined
template<int KSTEPS>
__device__ __forceinline__ void mm_atom(uint32_t aBase, uint32_t wBase,
                                        float (&acc)[4][4], uint32_t (&accL)[4][2],
                                        int lw, int lane) {
    const int warp_m = lw & 3, warp_n = lw >> 2;
    const int rsel = lane & 15, hsel = lane >> 4;
    uint32_t aAddr = aBase + (uint32_t)(((warp_m*16 + rsel) * PITCH + hsel*8) * 2);
    uint32_t wAddr = wBase + (uint32_t)(((warp_n*32 + rsel) * PITCH + hsel*8) * 2);
    const uint32_t STEP16 = 16 * PITCH * 2;

    uint32_t A[2][4], Wh[2][2][4], Wl[2][2][4];
    ldsm4(A[0], aAddr);
    ldsm4(Wh[0][0], wAddr);
    ldsm4(Wh[0][1], wAddr + STEP16);
    ldsm4(Wl[0][0], wAddr + IMG_W);
    ldsm4(Wl[0][1], wAddr + IMG_W + STEP16);

    #pragma unroll
    for (int kk = 0; kk < KSTEPS; kk++) {
        const int cur = kk & 1, nxt = cur ^ 1;
        if (kk + 1 < KSTEPS) {
            uint32_t ak = aAddr + (kk + 1) * 32;
            uint32_t wk = wAddr + (kk + 1) * 32;
            ldsm4(A[nxt], ak);
            ldsm4(Wh[nxt][0], wk);
            ldsm4(Wh[nxt][1], wk + STEP16);
            ldsm4(Wl[nxt][0], wk + IMG_W);
            ldsm4(Wl[nxt][1], wk + IMG_W + STEP16);
        }
        mma16816(acc[0], A[cur], Wh[cur][0][0], Wh[cur][0][2]);
        mma16816h(accL[0], A[cur], Wl[cur][0][0], Wl[cur][0][2]);
        mma16816(acc[1], A[cur], Wh[cur][0][1], Wh[cur][0][3]);
        mma16816h(accL[1], A[cur], Wl[cur][0][1], Wl[cur][0][3]);
        mma16816(acc[2], A[cur], Wh[cur][1][0], Wh[cur][1][2]);
        mma16816h(accL[2], A[cur], Wl[cur][1][0], Wl[cur][1][2]);
        mma16816(acc[3], A[cur], Wh[cur][1][1], Wh[cur][1][3]);
        mma16816h(accL[3], A[cur], Wl[cur][1][1], Wl[cur][1][3]);
    }
}

// stage epilogue (single atom, 64 rows, m16n32 tiles)
__device__ __forceinline__ void epilogue(
    int s, float (&acc)[4][4], uint32_t (&accL)[4][2], char* smem, int ba,
    int lw, int lane, const float (*sBias)[128],
    const float* sCut, const int* sNbr)
{
    const int warp_m = lw & 3, warp_n = lw >> 2;
    const int er = lane >> 2, ec2 = (lane & 3) * 2;
    char* dstH = smem + ((s == 2) ? VH_OFF : AH_OFF);
    float* vikT = reinterpret_cast<float*>(smem + VIK_OFF);
    const int bA = ba >> 8;
    #pragma unroll
    for (int nt = 0; nt < 4; nt++) {
        int col = warp_n*32 + nt*8 + ec2;
        float b0 = sBias[s][col], b1 = sBias[s][col + 1];
        #pragma unroll
        for (int h = 0; h < 2; h++) {
            int row = warp_m*16 + er + h*8;    // 0..63
            __half2 lo2 = *reinterpret_cast<__half2*>(&accL[nt][h]);
            float x0 = acc[nt][h*2+0] + __half2float(lo2.x) + b0;
            float x1 = acc[nt][h*2+1] + __half2float(lo2.y) + b1;
            if (s == 1) {
                float cu = sCut[row];
                const float2 y = *reinterpret_cast<const float2*>(
                    d_y + ((size_t)((bA << 8) + sNbr[row]) << 7) + col);
                x0 = x0 * cu * y.x;
                x1 = x1 * cu * y.y;
            } else if (s == 4) {
                *reinterpret_cast<float2*>(
                    d_vij + ((size_t)ba * 64 + row) * 128 + col) =
                    make_float2(x0, x1);
                continue;
            } else if (s == 6) {
                vikT[col * VPITCH + row]       = x0;
                vikT[(col + 1) * VPITCH + row] = x1;
                continue;
            } else {
                x0 = sspf(x0); x1 = sspf(x1);
            }
            __half2 hp = __floats2half2_rn(x0, x1);
            uint32_t off = (uint32_t)(row * PITCH + col) * 2;
            *reinterpret_cast<uint32_t*>(dstH + off) = *reinterpret_cast<uint32_t*>(&hp);
        }
    }
}

// ---------------- kernel: persistent fused interaction ---------------------
__global__ void __launch_bounds__(512, 1) k_main(
    const float* __restrict__ r_ij, const float* __restrict__ cos_ij,
    const float* __restrict__ f_ij, const float* __restrict__ nmask,
    const float* __restrict__ fb1, const float* __restrict__ fb2,
    const float* __restrict__ f2ob,
    const float* __restrict__ aW1, const float* __restrict__ ab1,
    const float* __restrict__ aW2, const float* __restrict__ ab2,
    const float* __restrict__ pb1, const float* __restrict__ pb2,
    const float* __restrict__ eb1, const float* __restrict__ eb2,
    const int* __restrict__ neighbors, float* __restrict__ out_vi)
{
    extern __shared__ char smem[];
    const uint32_t sb = smem_u32(smem);
    const int tid = threadIdx.x, lw = tid >> 5, lane = tid & 31;

    const int u0 = (blockIdx.x * NUNITS) / NCTA;
    const int u1 = ((blockIdx.x + 1) * NUNITS) / NCTA;
    const int nstages = (u1 - u0) * 7;

    __shared__ float sCut[64], sMask[64], cmS[192], vsumS[128], hidS[128];
    __shared__ float sBias[7][128];
    __shared__ int   sNbr[64];
    __shared__ __align__(8) uint64_t mbarW[2];
    const uint32_t mbarA[2] = { smem_u32(&mbarW[0]), smem_u32(&mbarW[1]) };

    if (tid == 0) {
        asm volatile("mbarrier.init.shared.b64 [%0], %1;" :: "r"(mbarA[0]), "r"(512u) : "memory");
        asm volatile("mbarrier.init.shared.b64 [%0], %1;" :: "r"(mbarA[1]), "r"(512u) : "memory");
    }
    {   // biases to smem
        const float* bp[7] = {fb1, fb2, f2ob, pb1, pb2, eb1, eb2};
        for (int i = tid; i < 7*128; i += 512)
            sBias[i >> 7][i & 127] = __ldg(bp[i >> 7] + (i & 127));
    }
    __syncthreads();   // mbar init visible

    // prime W pipeline: slices g=0,1
    #pragma unroll
    for (int g = 0; g < 2; g++) {
        const char* src = reinterpret_cast<const char*>(d_wsplit + (size_t)g * 2 * 128 * PITCH);
        uint32_t woff = g ? W1_OFF : W0_OFF;
        for (int i = tid * 16; i < (int)WBUF; i += 512*16)
            cp16(smem + woff + i, src + i);
        asm volatile("cp.async.mbarrier.arrive.noinc.shared.b64 [%0];"
                     :: "r"(mbarA[g]) : "memory");
    }

    float acc[4][4];
    uint32_t accL[4][2];
    int gg = 0;   // global slice counter (consumed)

    for (int u = u0; u < u1; u++) {
        const int ba = u;
        const int bA = ba >> 8;

        // per-unit scalars + feature scatter (Ah rows 0..63, cols 0..63)
        if (tid < 64) {
            int g = ba * NN + tid;
            float r = r_ij[g];
            sCut[tid]  = (r < 5.f) ? 0.5f * (__cosf(r * 0.62831853071795864f) + 1.f) : 0.f;
            float m = nmask[g];
            sMask[tid] = m;
            sNbr[tid]  = neighbors[g];
            cmS[tid*3+0] = cos_ij[(size_t)g*3+0] * m;
            cmS[tid*3+1] = cos_ij[(size_t)g*3+1] * m;
            cmS[tid*3+2] = cos_ij[(size_t)g*3+2] * m;
        }
        {
            const float* fg = f_ij + (size_t)ba * NN * NSB;
            __half* ah = reinterpret_cast<__half*>(smem);
            for (int i = tid; i < 64 * 64; i += 512) {
                int r = i >> 6, c = i & 63;
                float v = (c < NSB) ? fg[r * NSB + c] : 0.f;
                ah[r * PITCH + c] = __float2half_rn(v);
            }
        }
        __syncthreads();   // features + scalars ready

        for (int s = 0; s < 7; s++, gg++) {
            #pragma unroll
            for (int t = 0; t < 4; t++) {
                #pragma unroll
                for (int j = 0; j < 4; j++) acc[t][j] = 0.f;
                accL[t][0] = 0u; accL[t][1] = 0u;
            }
            mbar_wait(mbarA[gg & 1], (uint32_t)((gg >> 1) & 1));

            uint32_t aBase = sb + ((s == 3 || s == 5) ? VH_OFF : AH_OFF);
            uint32_t wBase = sb + ((gg & 1) ? W1_OFF : W0_OFF);
            if (s == 0) mm_atom<4>(aBase, wBase, acc, accL, lw, lane);
            else        mm_atom<8>(aBase, wBase, acc, accL, lw, lane);

            __syncthreads();   // all reads of A image + W buffer done

            int gn = gg + 2;
            if (gn < nstages) {   // refill just-freed buffer with slice gn
                int sn = gn % 7;
                const char* src = reinterpret_cast<const char*>(
                    d_wsplit + (size_t)sn * 2 * 128 * PITCH);
                uint32_t woff = (gn & 1) ? W1_OFF : W0_OFF;
                for (int i = tid * 16; i < (int)WBUF; i += 512*16)
                    cp16(smem + woff + i, src + i);
                asm volatile("cp.async.mbarrier.arrive.noinc.shared.b64 [%0];"
                             :: "r"(mbarA[gn & 1]) : "memory");
            }

            epilogue(s, acc, accL, smem, ba, lw, lane, sBias, sCut, sNbr);
            __syncthreads();   // epilogue writes visible
        }

        // ---- unit tail: Vik reduction, vsum, atom MLP (overlaps W prefetch) ----
        {
            const float* vikT = reinterpret_cast<const float*>(smem + VIK_OFF);
            if (tid < 384) {
                int c = tid / 3, d = tid - 3 * (tid / 3);
                float s = 0.f;
                #pragma unroll 4
                for (int n = 0; n < 64; n++)
                    s = fmaf(vikT[c * VPITCH + n], cmS[n * 3 + d], s);
                d_Vik[(size_t)ba * 384 + tid] = s;
            }
        }
        if (tid < 128) {
            const __half* vh = reinterpret_cast<const __half*>(smem + VH_OFF);
            float s = 0.f;
            #pragma unroll 4
            for (int n = 0; n < 64; n++)
                s = fmaf(__half2float(vh[n * PITCH + tid]), sMask[n], s);
            vsumS[tid] = s;
        }
        __syncthreads();
        if (tid < 128) {
            float h = __ldg(ab1 + tid);
            #pragma unroll 4
            for (int k = 0; k < 128; k++)
                h = fmaf(vsumS[k], __ldg(aW1 + k * 128 + tid), h);
            hidS[tid] = sspf(h);
        }
        __syncthreads();
        if (tid < 128) {
            float o = __ldg(ab2 + tid);
            #pragma unroll 4
            for (int k = 0; k < 128; k++)
                o = fmaf(hidS[k], __ldg(aW2 + k * 128 + tid), o);
            out_vi[(size_t)ba * NF + tid] = o;
        }
        __syncthreads();   // tail done before next unit's scalar overwrite
    }
}

// ---------------- kernel: assemble V (warp per idx, 12 floats/lane) --------
__global__ void __launch_bounds__(256) k_assemble(
    const float* __restrict__ cos_ij,
    const int* __restrict__ neighbors,
    float* __restrict__ outV) {
    int idx  = blockIdx.x * 8 + (threadIdx.x >> 5);
    int lane = threadIdx.x & 31;
    int ba   = idx >> 6;
    int b    = idx >> 14;
    int nb   = __ldg(neighbors + idx);
    int e0   = lane * 12;

    const float* vikL = d_Vik + (size_t)ba * 384 + e0;
    const float* vikN = d_Vik + ((size_t)(b * AA + nb)) * 384 + e0;
    float4 l0 = *reinterpret_cast<const float4*>(vikL);
    float4 l1 = *reinterpret_cast<const float4*>(vikL + 4);
    float4 l2 = *reinterpret_cast<const float4*>(vikL + 8);
    float4 n0 = *reinterpret_cast<const float4*>(vikN);
    float4 n1 = *reinterpret_cast<const float4*>(vikN + 4);
    float4 n2 = *reinterpret_cast<const float4*>(vikN + 8);
    float4 vij4 = __ldg(reinterpret_cast<const float4*>(d_vij + (size_t)idx * 128) + lane);
    float cc0 = __ldg(cos_ij + (size_t)idx * 3 + 0);
    float cc1 = __ldg(cos_ij + (size_t)idx * 3 + 1);
    float cc2 = __ldg(cos_ij + (size_t)idx * 3 + 2);

    float vs[12] = {l0.x+n0.x, l0.y+n0.y, l0.z+n0.z, l0.w+n0.w,
                    l1.x+n1.x, l1.y+n1.y, l1.z+n1.z, l1.w+n1.w,
                    l2.x+n2.x, l2.y+n2.y, l2.z+n2.z, l2.w+n2.w};
    float vij[4] = {vij4.x, vij4.y, vij4.z, vij4.w};
    float cc[3]  = {cc0, cc1, cc2};
    float o[12];
    #pragma unroll
    for (int j = 0; j < 12; j++) {
        int c = j / 3, d = j - 3 * c;
        o[j] = fmaf(vij[c], cc[d], vs[j]);
    }
    float* dst = outV + (size_t)idx * 384 + e0;
    *reinterpret_cast<float4*>(dst)     = make_float4(o[0], o[1], o[2],  o[3]);
    *reinterpret_cast<float4*>(dst + 4) = make_float4(o[4], o[5], o[6],  o[7]);
    *reinterpret_cast<float4*>(dst + 8) = make_float4(o[8], o[9], o[10], o[11]);
}

// ---------------- launch ----------------
extern "C" void kernel_launch(void* const* d_in, const int* in_sizes, int n_in,
                              void* d_out, int out_size) {
    const float* xi       = (const float*)d_in[0];
    const float* r_ij     = (const float*)d_in[1];
    const float* cos_ij   = (const float*)d_in[2];
    const float* f_ij     = (const float*)d_in[3];
    const float* nmask    = (const float*)d_in[4];
    const float* fW1      = (const float*)d_in[5];
    const float* fb1      = (const float*)d_in[6];
    const float* fW2      = (const float*)d_in[7];
    const float* fb2      = (const float*)d_in[8];
    const float* in2f_W   = (const float*)d_in[9];
    const float* f2oW     = (const float*)d_in[10];
    const float* f2ob     = (const float*)d_in[11];
    const float* aW1      = (const float*)d_in[12];
    const float* ab1      = (const float*)d_in[13];
    const float* aW2      = (const float*)d_in[14];
    const float* ab2      = (const float*)d_in[15];
    const float* pW1      = (const float*)d_in[16];
    const float* pb1      = (const float*)d_in[17];
    const float* pW2      = (const float*)d_in[18];
    const float* pb2      = (const float*)d_in[19];
    const float* eW1      = (const float*)d_in[20];
    const float* eb1      = (const float*)d_in[21];
    const float* eW2      = (const float*)d_in[22];
    const float* eb2      = (const float*)d_in[23];
    const int*   neighbors= (const int*)d_in[24];

    float* out = (float*)d_out;
    float* out_vi = out;                          // [B,A,NCB]
    float* out_V  = out + (size_t)BB*AA*NCB;      // [B,A,N,NCB,3]

    cudaFuncSetAttribute(k_init, cudaFuncAttributeMaxDynamicSharedMemorySize,
                         (int)INIT_SMEM);
    cudaFuncSetAttribute(k_main, cudaFuncAttributeMaxDynamicSharedMemorySize,
                         (int)SMEM_BYTES);

    k_init<<<7 + BB*AA/64, 256, INIT_SMEM>>>(fW1, fW2, f2oW, pW1, pW2, eW1, eW2,
                                             xi, in2f_W);
    k_main<<<NCTA, 512, SMEM_BYTES>>>(
        r_ij, cos_ij, f_ij, nmask,
        fb1, fb2, f2ob, aW1, ab1, aW2, ab2,
        pb1, pb2, eb1, eb2, neighbors, out_vi);
    k_assemble<<<BB*AA*NN/8, 256>>>(cos_ij, neighbors, out_V);
}

// round 15
// speedup vs baseline: 1.5878x; 1.4080x over previous
#include <cuda_runtime.h>
#include <cuda_fp16.h>
#include <stdint.h>

#define BB  4
#define AA  256
#define NN  64
#define NCB 128
#define NF  128
#define NSB 50

#define PITCH 136
#define IMG_A (64 * PITCH * 2)          // 17408
#define IMG_W (128 * PITCH * 2)         // 34816
#define ATOM_BLK (2 * IMG_A)            // 34816 (Ah, Vh per atom)
#define WBUF (2 * IMG_W)                // 69632 (hi + lo)
#define W0_OFF (2 * ATOM_BLK)           // 69632
#define W1_OFF (W0_OFF + WBUF)          // 139264
#define SMEM_BYTES (W1_OFF + WBUF)      // 208896
#define VPITCH 65
#define INIT_SMEM (IMG_A + 2 * IMG_W)   // 87040 (Ah + Wh + Wl)

// ---------------- global scratch ----------------
__device__ __align__(16) float d_y[BB*AA*NF];
__device__ __align__(16) float d_vij[(size_t)BB*AA*NN*NCB];
__device__ __align__(16) float d_Vik[BB*AA*NCB*3];
__device__ __align__(16) __half d_wsplit[7 * 2 * 128 * PITCH];

// ---------------- helpers ----------------
__device__ __forceinline__ void cp16(void* sdst, const void* gsrc) {
    unsigned s = (unsigned)__cvta_generic_to_shared(sdst);
    asm volatile("cp.async.cg.shared.global [%0], [%1], 16;" :: "r"(s), "l"(gsrc));
}
__device__ __forceinline__ void ldsm4(uint32_t* r, uint32_t saddr) {
    asm volatile("ldmatrix.sync.aligned.m8n8.x4.shared.b16 {%0,%1,%2,%3}, [%4];"
        : "=r"(r[0]), "=r"(r[1]), "=r"(r[2]), "=r"(r[3]) : "r"(saddr));
}
__device__ __forceinline__ void mma16816(float* c, const uint32_t* a,
                                         uint32_t b0, uint32_t b1) {
    asm volatile("mma.sync.aligned.m16n8k16.row.col.f32.f16.f16.f32 "
        "{%0,%1,%2,%3}, {%4,%5,%6,%7}, {%8,%9}, {%0,%1,%2,%3};"
        : "+f"(c[0]), "+f"(c[1]), "+f"(c[2]), "+f"(c[3])
        : "r"(a[0]), "r"(a[1]), "r"(a[2]), "r"(a[3]), "r"(b0), "r"(b1));
}
__device__ __forceinline__ void mma16816h(uint32_t* c, const uint32_t* a,
                                          uint32_t b0, uint32_t b1) {
    asm volatile("mma.sync.aligned.m16n8k16.row.col.f16.f16.f16.f16 "
        "{%0,%1}, {%2,%3,%4,%5}, {%6,%7}, {%0,%1};"
        : "+r"(c[0]), "+r"(c[1])
        : "r"(a[0]), "r"(a[1]), "r"(a[2]), "r"(a[3]), "r"(b0), "r"(b1));
}
__device__ __forceinline__ float sspf(float x) {
    if (x > 15.f) return x - 0.69314718055994531f;
    return __logf(1.f + __expf(x)) - 0.69314718055994531f;
}
__device__ __forceinline__ uint32_t smem_u32(const void* p) {
    return (uint32_t)__cvta_generic_to_shared(p);
}
__device__ __forceinline__ void mbar_wait(uint32_t mb, uint32_t parity) {
    uint32_t done;
    asm volatile("{\n\t.reg .pred p;\n\t"
        "mbarrier.try_wait.parity.acquire.cta.shared::cta.b64 p, [%1], %2;\n\t"
        "selp.b32 %0, 1, 0, p;\n\t}"
        : "=r"(done) : "r"(mb), "r"(parity) : "memory");
    if (!done) {
        asm volatile("{\n\t.reg .pred P1;\n\t"
            "W_%=:\n\t"
            "mbarrier.try_wait.parity.acquire.cta.shared::cta.b64 P1, [%0], %1, 0x989680;\n\t"
            "@P1 bra.uni D_%=;\n\t"
            "bra.uni W_%=;\n\t"
            "D_%=:\n\t}"
            :: "r"(mb), "r"(parity) : "memory");
    }
}

// 2-product GEMM, m32n32 warp tile, software-pipelined k-loop.
template<int KSTEPS>
__device__ __forceinline__ void mm(uint32_t aBase, uint32_t wBase,
                                   float (&acc)[8][4], uint32_t (&accL)[8][2],
                                   int lw, int lane) {
    const int warp_m = (lw >> 2) & 1, warp_n = lw & 3;
    const int rsel = lane & 15, hsel = lane >> 4;
    uint32_t aAddr = aBase + (uint32_t)(((warp_m*32 + rsel) * PITCH + hsel*8) * 2);
    uint32_t wAddr = wBase + (uint32_t)(((warp_n*32 + rsel) * PITCH + hsel*8) * 2);
    const uint32_t STEP16 = 16 * PITCH * 2;

    uint32_t A[2][2][4], Wh[2][2][4], Wl[2][2][4];
    ldsm4(A[0][0],  aAddr);
    ldsm4(A[0][1],  aAddr + STEP16);
    ldsm4(Wh[0][0], wAddr);
    ldsm4(Wh[0][1], wAddr + STEP16);
    ldsm4(Wl[0][0], wAddr + IMG_W);
    ldsm4(Wl[0][1], wAddr + IMG_W + STEP16);

    #pragma unroll
    for (int kk = 0; kk < KSTEPS; kk++) {
        const int cur = kk & 1, nxt = cur ^ 1;
        if (kk + 1 < KSTEPS) {
            uint32_t ak = aAddr + (kk + 1) * 32;
            uint32_t wk = wAddr + (kk + 1) * 32;
            ldsm4(A[nxt][0],  ak);
            ldsm4(A[nxt][1],  ak + STEP16);
            ldsm4(Wh[nxt][0], wk);
            ldsm4(Wh[nxt][1], wk + STEP16);
            ldsm4(Wl[nxt][0], wk + IMG_W);
            ldsm4(Wl[nxt][1], wk + IMG_W + STEP16);
        }
        #pragma unroll
        for (int mt = 0; mt < 2; mt++)
            #pragma unroll
            for (int q = 0; q < 2; q++)
                #pragma unroll
                for (int j = 0; j < 2; j++) {
                    int t = mt*4 + q*2 + j;
                    mma16816(acc[t],  A[cur][mt], Wh[cur][q][j], Wh[cur][q][j+2]);
                    mma16816h(accL[t], A[cur][mt], Wl[cur][q][j], Wl[cur][q][j+2]);
                }
    }
}

// ---------------- kernel: weight prep (blocks 0-6) + HMMA embed (7-22) -----
__global__ void __launch_bounds__(256) k_init(
    const float* fW1, const float* fW2, const float* f2oW,
    const float* pW1, const float* pW2, const float* eW1, const float* eW2,
    const float* __restrict__ xi, const float* __restrict__ in2f_W) {
    extern __shared__ char sdyn[];
    int bid = blockIdx.x;
    int tid = threadIdx.x;
    if (bid < 7) {
        const float* W; int K, realK;
        switch (bid) {
            case 0: W = fW1;  K = 64;  realK = NSB; break;
            case 1: W = fW2;  K = 128; realK = 128; break;
            case 2: W = f2oW; K = 128; realK = 128; break;
            case 3: W = pW1;  K = 128; realK = 128; break;
            case 4: W = pW2;  K = 128; realK = 128; break;
            case 5: W = eW1;  K = 128; realK = 128; break;
            default: W = eW2; K = 128; realK = 128; break;
        }
        __half* hi = d_wsplit + (size_t)bid * 2 * 128 * PITCH;
        __half* lo = hi + 128 * PITCH;
        for (int i = tid; i < 128 * K; i += 256) {
            int n = i / K, k = i - (i / K) * K;
            float v = (k < realK) ? W[k * 128 + n] : 0.f;   // B^T: [n][k]
            __half h = __float2half_rn(v);
            hi[n * PITCH + k] = h;
            lo[n * PITCH + k] = __float2half_rn(v - __half2float(h));
        }
    } else {
        // HMMA embed: 64 rows per block; d_y = xi @ in2f_W (fp16 2-product)
        const int row0 = (bid - 7) * 64;
        __half* Ah = reinterpret_cast<__half*>(sdyn);
        __half* Wh = reinterpret_cast<__half*>(sdyn + IMG_A);
        __half* Wl = Wh + 128 * PITCH;
        for (int i = tid; i < 64 * 128; i += 256) {
            int r = i >> 7, c = i & 127;
            Ah[r * PITCH + c] = __float2half_rn(xi[(size_t)(row0 + r) * 128 + c]);
        }
        for (int i = tid; i < 128 * 128; i += 256) {
            int k = i >> 7, n = i & 127;
            float v = __ldg(in2f_W + i);
            __half h = __float2half_rn(v);
            Wh[n * PITCH + k] = h;
            Wl[n * PITCH + k] = __float2half_rn(v - __half2float(h));
        }
        __syncthreads();

        float acc[8][4];
        uint32_t accL[8][2];
        #pragma unroll
        for (int t = 0; t < 8; t++) {
            #pragma unroll
            for (int j = 0; j < 4; j++) acc[t][j] = 0.f;
            accL[t][0] = 0u; accL[t][1] = 0u;
        }
        const uint32_t sbi = smem_u32(sdyn);
        const int lw = tid >> 5, lane = tid & 31;
        mm<8>(sbi, sbi + IMG_A, acc, accL, lw, lane);

        const int warp_m = (lw >> 2) & 1, warp_n = lw & 3;
        const int er = lane >> 2, ec2 = (lane & 3) * 2;
        #pragma unroll
        for (int mt = 0; mt < 2; mt++)
            #pragma unroll
            for (int nt = 0; nt < 4; nt++) {
                int t = mt*4 + nt;
                int col = warp_n*32 + nt*8 + ec2;
                #pragma unroll
                for (int h = 0; h < 2; h++) {
                    int row = warp_m*32 + mt*16 + er + h*8;
                    __half2 lo2 = *reinterpret_cast<__half2*>(&accL[t][h]);
                    float x0 = acc[t][h*2+0] + __half2float(lo2.x);
                    float x1 = acc[t][h*2+1] + __half2float(lo2.y);
                    *reinterpret_cast<float2*>(
                        d_y + (size_t)(row0 + row) * 128 + col) = make_float2(x0, x1);
                }
            }
    }
}

// stage epilogue for one pipeline (m32n32 tile mapping)
__device__ __forceinline__ void epilogue(
    int s, float (&acc)[8][4], uint32_t (&accL)[8][2], char* smem, int pid, int ba0,
    int lw, int lane, const float (*sBias)[128],
    const float* sCut, const int* sNbr)
{
    const int warp_m = (lw >> 2) & 1, warp_n = lw & 3;
    const int er = lane >> 2, ec2 = (lane & 3) * 2;
    char* atomBase = smem + pid * ATOM_BLK;
    char* dstH = atomBase + ((s == 2) ? IMG_A : 0);
    float* vikT = reinterpret_cast<float*>(smem + W1_OFF + pid * IMG_W);
    const int baG = ba0 + pid;
    const int bA = baG >> 8;
    #pragma unroll
    for (int mt = 0; mt < 2; mt++) {
        #pragma unroll
        for (int nt = 0; nt < 4; nt++) {
            int t = mt*4 + nt;
            int col = warp_n*32 + nt*8 + ec2;
            float b0 = sBias[s][col], b1 = sBias[s][col + 1];
            #pragma unroll
            for (int h = 0; h < 2; h++) {
                int row = warp_m*32 + mt*16 + er + h*8;   // 0..63
                int grow = pid*64 + row;
                __half2 lo2 = *reinterpret_cast<__half2*>(&accL[t][h]);
                float x0 = acc[t][h*2+0] + __half2float(lo2.x) + b0;
                float x1 = acc[t][h*2+1] + __half2float(lo2.y) + b1;
                if (s == 1) {
                    float cu = sCut[grow];
                    const float2 y = *reinterpret_cast<const float2*>(
                        d_y + ((size_t)((bA << 8) + sNbr[grow]) << 7) + col);
                    x0 = x0 * cu * y.x;
                    x1 = x1 * cu * y.y;
                } else if (s == 4) {
                    *reinterpret_cast<float2*>(
                        d_vij + ((size_t)baG * 64 + row) * 128 + col) =
                        make_float2(x0, x1);
                    continue;
                } else if (s == 6) {
                    vikT[col * VPITCH + row]       = x0;
                    vikT[(col + 1) * VPITCH + row] = x1;
                    continue;
                } else {
                    x0 = sspf(x0); x1 = sspf(x1);
                }
                __half2 hp = __floats2half2_rn(x0, x1);
                uint32_t off = (uint32_t)(row * PITCH + col) * 2;
                *reinterpret_cast<uint32_t*>(dstH + off) = *reinterpret_cast<uint32_t*>(&hp);
            }
        }
    }
}

// ---------------- kernel: fused interaction, double-buffered W -------------
__global__ void __launch_bounds__(512, 1) k_main(
    const float* __restrict__ r_ij, const float* __restrict__ cos_ij,
    const float* __restrict__ f_ij, const float* __restrict__ nmask,
    const float* __restrict__ fb1, const float* __restrict__ fb2,
    const float* __restrict__ f2ob,
    const float* __restrict__ aW1, const float* __restrict__ ab1,
    const float* __restrict__ aW2, const float* __restrict__ ab2,
    const float* __restrict__ pb1, const float* __restrict__ pb2,
    const float* __restrict__ eb1, const float* __restrict__ eb2,
    const int* __restrict__ neighbors, float* __restrict__ out_vi)
{
    extern __shared__ char smem[];
    const uint32_t sb = smem_u32(smem);
    const int tid = threadIdx.x;
    const int pid = tid >> 8;            // pipeline/atom: 0 or 1
    const int lt  = tid & 255, lw = lt >> 5, lane = tid & 31;
    const int ba0 = blockIdx.x * 2;

    __shared__ float sCut[128], sMask[128], cmS[384], vsumS[256], hidS[256];
    __shared__ float partS[512];
    __shared__ float sBias[7][128];
    __shared__ int   sNbr[128];
    __shared__ __align__(8) uint64_t mbarW[2];
    const uint32_t mbar0 = smem_u32(&mbarW[0]);
    const uint32_t mbar1 = smem_u32(&mbarW[1]);

    if (tid == 0) {
        asm volatile("mbarrier.init.shared.b64 [%0], %1;" :: "r"(mbar0), "r"(512u) : "memory");
        asm volatile("mbarrier.init.shared.b64 [%0], %1;" :: "r"(mbar1), "r"(512u) : "memory");
    }

    {   // biases to smem
        const float* bp[7] = {fb1, fb2, f2ob, pb1, pb2, eb1, eb2};
        for (int i = tid; i < 7*128; i += 512)
            sBias[i >> 7][i & 127] = __ldg(bp[i >> 7] + (i & 127));
    }
    if (tid < 128) {
        int g = ba0 * NN + tid;
        float r = r_ij[g];
        sCut[tid]  = (r < 5.f) ? 0.5f * (__cosf(r * 0.62831853071795864f) + 1.f) : 0.f;
        float m = nmask[g];
        sMask[tid] = m;
        sNbr[tid]  = neighbors[g];
        cmS[tid*3+0] = cos_ij[(size_t)g*3+0] * m;
        cmS[tid*3+1] = cos_ij[(size_t)g*3+1] * m;
        cmS[tid*3+2] = cos_ij[(size_t)g*3+2] * m;
    }
    {   // zero both atoms' images
        uint64_t* z = reinterpret_cast<uint64_t*>(smem);
        for (int i = tid; i < (2*ATOM_BLK)/8; i += 512) z[i] = 0ull;
    }
    __syncthreads();   // mbar init + zero visible

    {   // issue W(0) -> buf0
        const char* src = reinterpret_cast<const char*>(d_wsplit);
        for (int i = tid * 16; i < WBUF; i += 512*16)
            cp16(smem + W0_OFF + i, src + i);
        asm volatile("cp.async.mbarrier.arrive.noinc.shared.b64 [%0];"
                     :: "r"(mbar0) : "memory");
    }
    {   // scatter features (fp16)
        const float* fg = f_ij + (size_t)(ba0 + pid) * NN * NSB;
        __half* ah = reinterpret_cast<__half*>(smem + pid * ATOM_BLK);
        for (int i = lt; i < NN * NSB; i += 256) {
            int r = i / NSB, c = i - (i / NSB) * NSB;
            ah[r * PITCH + c] = __float2half_rn(fg[i]);
        }
    }
    __syncthreads();   // feature images ready

    float acc[8][4];
    uint32_t accL[8][2];

    for (int s = 0; s < 7; s++) {
        // issue W(s+1) into the other buffer — a full stage of lead
        if (s < 6) {
            const char* src = reinterpret_cast<const char*>(
                d_wsplit + (size_t)(s + 1) * 2 * 128 * PITCH);
            uint32_t woff = ((s + 1) & 1) ? W1_OFF : W0_OFF;
            for (int i = tid * 16; i < WBUF; i += 512*16)
                cp16(smem + woff + i, src + i);
            asm volatile("cp.async.mbarrier.arrive.noinc.shared.b64 [%0];"
                         :: "r"(((s + 1) & 1) ? mbar1 : mbar0) : "memory");
        }

        // Q: epilogue of previous stage overlaps P's MMAs
        if (pid == 1 && s > 0) {
            epilogue(s - 1, acc, accL, smem, 1, ba0, lw, lane, sBias, sCut, sNbr);
            asm volatile("bar.sync 2, 256;" ::: "memory");   // Q-internal
        }
        #pragma unroll
        for (int t = 0; t < 8; t++) {
            #pragma unroll
            for (int j = 0; j < 4; j++) acc[t][j] = 0.f;
            accL[t][0] = 0u; accL[t][1] = 0u;
        }

        mbar_wait((s & 1) ? mbar1 : mbar0, (uint32_t)((s >> 1) & 1));

        uint32_t aBase = sb + pid * ATOM_BLK + ((s == 3 || s == 5) ? IMG_A : 0);
        uint32_t wBase = sb + ((s & 1) ? W1_OFF : W0_OFF);
        if (s == 0) mm<4>(aBase, wBase, acc, accL, lw, lane);
        else        mm<8>(aBase, wBase, acc, accL, lw, lane);

        // P: epilogue overlaps Q's MMAs
        if (pid == 0 && s < 6)
            epilogue(s, acc, accL, smem, 0, ba0, lw, lane, sBias, sCut, sNbr);

        __syncthreads();
    }

    // stage-6 epilogues (both pipelines) -> vikT in W1 buffer
    epilogue(6, acc, accL, smem, pid, ba0, lw, lane, sBias, sCut, sNbr);
    __syncthreads();

    // ---- Vik[c][d] = sum_n vik[n][c] * cm[n][d] (both atoms) ----
    for (int e = tid; e < 768; e += 512) {
        int atom = e / 384, rem = e - atom * 384;
        int c = rem / 3, d = rem - 3 * (rem / 3);
        const float* vikT = reinterpret_cast<const float*>(smem + W1_OFF + atom * IMG_W);
        float s = 0.f;
        #pragma unroll 8
        for (int n = 0; n < 64; n++)
            s = fmaf(vikT[c * VPITCH + n], cmS[(atom*64 + n) * 3 + d], s);
        d_Vik[(size_t)(ba0 + atom) * 384 + rem] = s;
    }

    // ---- vsum from V (fp16 image) ----
    if (tid < 256) {
        int atom = tid >> 7, c = tid & 127;
        const __half* vh = reinterpret_cast<const __half*>(smem + atom*ATOM_BLK + IMG_A);
        float s = 0.f;
        #pragma unroll 8
        for (int n = 0; n < 64; n++)
            s = fmaf(__half2float(vh[n * PITCH + c]), sMask[atom*64 + n], s);
        vsumS[tid] = s;
    }
    __syncthreads();

    // ---- atom MLP layer 1: 512-thread split-k partials ----
    {
        int atom = tid >> 8, half = (tid >> 7) & 1, c = tid & 127;
        const float* vs = vsumS + atom * 128 + half * 64;
        const float* w  = aW1 + (half * 64) * 128 + c;
        float h = 0.f;
        #pragma unroll 8
        for (int k = 0; k < 64; k++)
            h = fmaf(vs[k], __ldg(w + k * 128), h);
        partS[tid] = h;
    }
    __syncthreads();
    if (tid < 256) {
        int atom = tid >> 7, c = tid & 127;
        hidS[tid] = sspf(partS[atom*256 + c] + partS[atom*256 + 128 + c] + __ldg(ab1 + c));
    }
    __syncthreads();

    // ---- atom MLP layer 2: 512-thread split-k partials ----
    {
        int atom = tid >> 8, half = (tid >> 7) & 1, c = tid & 127;
        const float* hs = hidS + atom * 128 + half * 64;
        const float* w  = aW2 + (half * 64) * 128 + c;
        float o = 0.f;
        #pragma unroll 8
        for (int k = 0; k < 64; k++)
            o = fmaf(hs[k], __ldg(w + k * 128), o);
        partS[tid] = o;
    }
    __syncthreads();
    if (tid < 256) {
        int atom = tid >> 7, c = tid & 127;
        out_vi[(size_t)(ba0 + atom) * NF + c] =
            partS[atom*256 + c] + partS[atom*256 + 128 + c] + __ldg(ab2 + c);
    }
}

// ---------------- kernel: assemble V (warp per idx, 12 floats/lane) --------
__global__ void __launch_bounds__(256) k_assemble(
    const float* __restrict__ cos_ij,
    const int* __restrict__ neighbors,
    float* __restrict__ outV) {
    int idx  = blockIdx.x * 8 + (threadIdx.x >> 5);   // (b,a,n) flat
    int lane = threadIdx.x & 31;
    int ba   = idx >> 6;
    int b    = idx >> 14;
    int nb   = __ldg(neighbors + idx);
    int e0   = lane * 12;

    const float* vikL = d_Vik + (size_t)ba * 384 + e0;
    const float* vikN = d_Vik + ((size_t)(b * AA + nb)) * 384 + e0;
    float4 l0 = *reinterpret_cast<const float4*>(vikL);
    float4 l1 = *reinterpret_cast<const float4*>(vikL + 4);
    float4 l2 = *reinterpret_cast<const float4*>(vikL + 8);
    float4 n0 = *reinterpret_cast<const float4*>(vikN);
    float4 n1 = *reinterpret_cast<const float4*>(vikN + 4);
    float4 n2 = *reinterpret_cast<const float4*>(vikN + 8);
    float4 vij4 = __ldg(reinterpret_cast<const float4*>(d_vij + (size_t)idx * 128) + lane);
    float cc0 = __ldg(cos_ij + (size_t)idx * 3 + 0);
    float cc1 = __ldg(cos_ij + (size_t)idx * 3 + 1);
    float cc2 = __ldg(cos_ij + (size_t)idx * 3 + 2);

    float vs[12] = {l0.x+n0.x, l0.y+n0.y, l0.z+n0.z, l0.w+n0.w,
                    l1.x+n1.x, l1.y+n1.y, l1.z+n1.z, l1.w+n1.w,
                    l2.x+n2.x, l2.y+n2.y, l2.z+n2.z, l2.w+n2.w};
    float vij[4] = {vij4.x, vij4.y, vij4.z, vij4.w};
    float cc[3]  = {cc0, cc1, cc2};
    float o[12];
    #pragma unroll
    for (int j = 0; j < 12; j++) {
        int c = j / 3, d = j - 3 * c;
        o[j] = fmaf(vij[c], cc[d], vs[j]);
    }
    float* dst = outV + (size_t)idx * 384 + e0;
    *reinterpret_cast<float4*>(dst)     = make_float4(o[0], o[1], o[2],  o[3]);
    *reinterpret_cast<float4*>(dst + 4) = make_float4(o[4], o[5], o[6],  o[7]);
    *reinterpret_cast<float4*>(dst + 8) = make_float4(o[8], o[9], o[10], o[11]);
}

// ---------------- launch ----------------
extern "C" void kernel_launch(void* const* d_in, const int* in_sizes, int n_in,
                              void* d_out, int out_size) {
    const float* xi       = (const float*)d_in[0];
    const float* r_ij     = (const float*)d_in[1];
    const float* cos_ij   = (const float*)d_in[2];
    const float* f_ij     = (const float*)d_in[3];
    const float* nmask    = (const float*)d_in[4];
    const float* fW1      = (const float*)d_in[5];
    const float* fb1      = (const float*)d_in[6];
    const float* fW2      = (const float*)d_in[7];
    const float* fb2      = (const float*)d_in[8];
    const float* in2f_W   = (const float*)d_in[9];
    const float* f2oW     = (const float*)d_in[10];
    const float* f2ob     = (const float*)d_in[11];
    const float* aW1      = (const float*)d_in[12];
    const float* ab1      = (const float*)d_in[13];
    const float* aW2      = (const float*)d_in[14];
    const float* ab2      = (const float*)d_in[15];
    const float* pW1      = (const float*)d_in[16];
    const float* pb1      = (const float*)d_in[17];
    const float* pW2      = (const float*)d_in[18];
    const float* pb2      = (const float*)d_in[19];
    const float* eW1      = (const float*)d_in[20];
    const float* eb1      = (const float*)d_in[21];
    const float* eW2      = (const float*)d_in[22];
    const float* eb2      = (const float*)d_in[23];
    const int*   neighbors= (const int*)d_in[24];

    float* out = (float*)d_out;
    float* out_vi = out;                          // [B,A,NCB]
    float* out_V  = out + (size_t)BB*AA*NCB;      // [B,A,N,NCB,3]

    cudaFuncSetAttribute(k_init, cudaFuncAttributeMaxDynamicSharedMemorySize,
                         (int)INIT_SMEM);
    cudaFuncSetAttribute(k_main, cudaFuncAttributeMaxDynamicSharedMemorySize,
                         (int)SMEM_BYTES);

    k_init<<<7 + BB*AA/64, 256, INIT_SMEM>>>(fW1, fW2, f2oW, pW1, pW2, eW1, eW2,
                                             xi, in2f_W);
    k_main<<<BB*AA/2, 512, SMEM_BYTES>>>(
        r_ij, cos_ij, f_ij, nmask,
        fb1, fb2, f2ob, aW1, ab1, aW2, ab2,
        pb1, pb2, eb1, eb2, neighbors, out_vi);
    k_assemble<<<BB*AA*NN/8, 256>>>(cos_ij, neighbors, out_V);
}

// round 16
// speedup vs baseline: 1.7005x; 1.0709x over previous
#include <cuda_runtime.h>
#include <cuda_fp16.h>
#include <stdint.h>

#define BB  4
#define AA  256
#define NN  64
#define NCB 128
#define NF  128
#define NSB 50

#define PITCH 136
#define IMG_A (64 * PITCH * 2)          // 17408
#define IMG_W (128 * PITCH * 2)         // 34816
#define ATOM_BLK (2 * IMG_A)            // 34816 (Ah, Vh per atom)
#define WBUF (2 * IMG_W)                // 69632 (hi + lo)
#define W0_OFF (2 * ATOM_BLK)           // 69632
#define W1_OFF (W0_OFF + WBUF)          // 139264
#define SMEM_BYTES (W1_OFF + WBUF)      // 208896
#define VPITCH 65
#define INIT_SMEM (IMG_A + 2 * IMG_W)   // 87040 (Ah + Wh + Wl)

// ---------------- global scratch ----------------
__device__ __align__(16) float d_y[BB*AA*NF];
__device__ __align__(16) float d_vij[(size_t)BB*AA*NN*NCB];
__device__ __align__(16) float d_Vik[BB*AA*NCB*3];
__device__ __align__(16) __half d_wsplit[7 * 2 * 128 * PITCH];

// ---------------- helpers ----------------
__device__ __forceinline__ void cp16(void* sdst, const void* gsrc) {
    unsigned s = (unsigned)__cvta_generic_to_shared(sdst);
    asm volatile("cp.async.cg.shared.global [%0], [%1], 16;" :: "r"(s), "l"(gsrc));
}
__device__ __forceinline__ void ldsm4(uint32_t* r, uint32_t saddr) {
    asm volatile("ldmatrix.sync.aligned.m8n8.x4.shared.b16 {%0,%1,%2,%3}, [%4];"
        : "=r"(r[0]), "=r"(r[1]), "=r"(r[2]), "=r"(r[3]) : "r"(saddr));
}
__device__ __forceinline__ void mma16816(float* c, const uint32_t* a,
                                         uint32_t b0, uint32_t b1) {
    asm volatile("mma.sync.aligned.m16n8k16.row.col.f32.f16.f16.f32 "
        "{%0,%1,%2,%3}, {%4,%5,%6,%7}, {%8,%9}, {%0,%1,%2,%3};"
        : "+f"(c[0]), "+f"(c[1]), "+f"(c[2]), "+f"(c[3])
        : "r"(a[0]), "r"(a[1]), "r"(a[2]), "r"(a[3]), "r"(b0), "r"(b1));
}
__device__ __forceinline__ void mma16816h(uint32_t* c, const uint32_t* a,
                                          uint32_t b0, uint32_t b1) {
    asm volatile("mma.sync.aligned.m16n8k16.row.col.f16.f16.f16.f16 "
        "{%0,%1}, {%2,%3,%4,%5}, {%6,%7}, {%0,%1};"
        : "+r"(c[0]), "+r"(c[1])
        : "r"(a[0]), "r"(a[1]), "r"(a[2]), "r"(a[3]), "r"(b0), "r"(b1));
}
__device__ __forceinline__ float sspf(float x) {
    if (x > 15.f) return x - 0.69314718055994531f;
    return __logf(1.f + __expf(x)) - 0.69314718055994531f;
}
__device__ __forceinline__ uint32_t smem_u32(const void* p) {
    return (uint32_t)__cvta_generic_to_shared(p);
}
__device__ __forceinline__ void mbar_wait(uint32_t mb, uint32_t parity) {
    uint32_t done;
    asm volatile("{\n\t.reg .pred p;\n\t"
        "mbarrier.try_wait.parity.acquire.cta.shared::cta.b64 p, [%1], %2;\n\t"
        "selp.b32 %0, 1, 0, p;\n\t}"
        : "=r"(done) : "r"(mb), "r"(parity) : "memory");
    if (!done) {
        asm volatile("{\n\t.reg .pred P1;\n\t"
            "W_%=:\n\t"
            "mbarrier.try_wait.parity.acquire.cta.shared::cta.b64 P1, [%0], %1, 0x989680;\n\t"
            "@P1 bra.uni D_%=;\n\t"
            "bra.uni W_%=;\n\t"
            "D_%=:\n\t}"
            :: "r"(mb), "r"(parity) : "memory");
    }
}

// 2-product (or hi-only) GEMM, m32n32 warp tile, software-pipelined k-loop.
template<int KSTEPS, bool LO>
__device__ __forceinline__ void mm(uint32_t aBase, uint32_t wBase,
                                   float (&acc)[8][4], uint32_t (&accL)[8][2],
                                   int lw, int lane) {
    const int warp_m = (lw >> 2) & 1, warp_n = lw & 3;
    const int rsel = lane & 15, hsel = lane >> 4;
    uint32_t aAddr = aBase + (uint32_t)(((warp_m*32 + rsel) * PITCH + hsel*8) * 2);
    uint32_t wAddr = wBase + (uint32_t)(((warp_n*32 + rsel) * PITCH + hsel*8) * 2);
    const uint32_t STEP16 = 16 * PITCH * 2;

    uint32_t A[2][2][4], Wh[2][2][4], Wl[2][2][4];
    ldsm4(A[0][0],  aAddr);
    ldsm4(A[0][1],  aAddr + STEP16);
    ldsm4(Wh[0][0], wAddr);
    ldsm4(Wh[0][1], wAddr + STEP16);
    if (LO) {
        ldsm4(Wl[0][0], wAddr + IMG_W);
        ldsm4(Wl[0][1], wAddr + IMG_W + STEP16);
    }

    #pragma unroll
    for (int kk = 0; kk < KSTEPS; kk++) {
        const int cur = kk & 1, nxt = cur ^ 1;
        if (kk + 1 < KSTEPS) {
            uint32_t ak = aAddr + (kk + 1) * 32;
            uint32_t wk = wAddr + (kk + 1) * 32;
            ldsm4(A[nxt][0],  ak);
            ldsm4(A[nxt][1],  ak + STEP16);
            ldsm4(Wh[nxt][0], wk);
            ldsm4(Wh[nxt][1], wk + STEP16);
            if (LO) {
                ldsm4(Wl[nxt][0], wk + IMG_W);
                ldsm4(Wl[nxt][1], wk + IMG_W + STEP16);
            }
        }
        #pragma unroll
        for (int mt = 0; mt < 2; mt++)
            #pragma unroll
            for (int q = 0; q < 2; q++)
                #pragma unroll
                for (int j = 0; j < 2; j++) {
                    int t = mt*4 + q*2 + j;
                    mma16816(acc[t],  A[cur][mt], Wh[cur][q][j], Wh[cur][q][j+2]);
                    if (LO)
                        mma16816h(accL[t], A[cur][mt], Wl[cur][q][j], Wl[cur][q][j+2]);
                }
    }
}

// ---------------- kernel: weight prep (blocks 0-13) + HMMA embed (14-29) ---
__global__ void __launch_bounds__(256) k_init(
    const float* fW1, const float* fW2, const float* f2oW,
    const float* pW1, const float* pW2, const float* eW1, const float* eW2,
    const float* __restrict__ xi, const float* __restrict__ in2f_W) {
    extern __shared__ char sdyn[];
    int bid = blockIdx.x;
    int tid = threadIdx.x;
    if (bid < 14) {
        int st = bid >> 1, half = bid & 1;
        const float* W; int K, realK;
        switch (st) {
            case 0: W = fW1;  K = 64;  realK = NSB; break;
            case 1: W = fW2;  K = 128; realK = 128; break;
            case 2: W = f2oW; K = 128; realK = 128; break;
            case 3: W = pW1;  K = 128; realK = 128; break;
            case 4: W = pW2;  K = 128; realK = 128; break;
            case 5: W = eW1;  K = 128; realK = 128; break;
            default: W = eW2; K = 128; realK = 128; break;
        }
        int k0 = half * 64;
        if (k0 >= K) return;
        __half* hi = d_wsplit + (size_t)st * 2 * 128 * PITCH;
        __half* lo = hi + 128 * PITCH;
        // 128 n x 32 k-pairs; consecutive threads -> consecutive n (coalesced LDG)
        for (int i = tid; i < 128 * 32; i += 256) {
            int kp = i >> 7, n = i & 127;
            int k = k0 + kp * 2;
            float v0 = (k     < realK) ? W[(size_t)k       * 128 + n] : 0.f;
            float v1 = (k + 1 < realK) ? W[(size_t)(k + 1) * 128 + n] : 0.f;
            __half h0 = __float2half_rn(v0);
            __half h1 = __float2half_rn(v1);
            __half2 hp; hp.x = h0; hp.y = h1;
            __half2 lp = __floats2half2_rn(v0 - __half2float(h0),
                                           v1 - __half2float(h1));
            *reinterpret_cast<__half2*>(hi + (size_t)n * PITCH + k) = hp;
            *reinterpret_cast<__half2*>(lo + (size_t)n * PITCH + k) = lp;
        }
    } else {
        // HMMA embed: 64 rows per block; d_y = xi @ in2f_W (fp16 2-product)
        const int row0 = (bid - 14) * 64;
        __half* Ah = reinterpret_cast<__half*>(sdyn);
        __half* Wh = reinterpret_cast<__half*>(sdyn + IMG_A);
        __half* Wl = Wh + 128 * PITCH;
        for (int i = tid; i < 64 * 128; i += 256) {
            int r = i >> 7, c = i & 127;
            Ah[r * PITCH + c] = __float2half_rn(xi[(size_t)(row0 + r) * 128 + c]);
        }
        for (int i = tid; i < 128 * 128; i += 256) {
            int k = i >> 7, n = i & 127;
            float v = __ldg(in2f_W + i);
            __half h = __float2half_rn(v);
            Wh[n * PITCH + k] = h;
            Wl[n * PITCH + k] = __float2half_rn(v - __half2float(h));
        }
        __syncthreads();

        float acc[8][4];
        uint32_t accL[8][2];
        #pragma unroll
        for (int t = 0; t < 8; t++) {
            #pragma unroll
            for (int j = 0; j < 4; j++) acc[t][j] = 0.f;
            accL[t][0] = 0u; accL[t][1] = 0u;
        }
        const uint32_t sbi = smem_u32(sdyn);
        const int lw = tid >> 5, lane = tid & 31;
        mm<8, true>(sbi, sbi + IMG_A, acc, accL, lw, lane);

        const int warp_m = (lw >> 2) & 1, warp_n = lw & 3;
        const int er = lane >> 2, ec2 = (lane & 3) * 2;
        #pragma unroll
        for (int mt = 0; mt < 2; mt++)
            #pragma unroll
            for (int nt = 0; nt < 4; nt++) {
                int t = mt*4 + nt;
                int col = warp_n*32 + nt*8 + ec2;
                #pragma unroll
                for (int h = 0; h < 2; h++) {
                    int row = warp_m*32 + mt*16 + er + h*8;
                    __half2 lo2 = *reinterpret_cast<__half2*>(&accL[t][h]);
                    float x0 = acc[t][h*2+0] + __half2float(lo2.x);
                    float x1 = acc[t][h*2+1] + __half2float(lo2.y);
                    *reinterpret_cast<float2*>(
                        d_y + (size_t)(row0 + row) * 128 + col) = make_float2(x0, x1);
                }
            }
    }
}

// stage epilogue for one pipeline (m32n32 tile mapping)
__device__ __forceinline__ void epilogue(
    int s, float (&acc)[8][4], uint32_t (&accL)[8][2], char* smem, int pid, int ba0,
    int lw, int lane, const float (*sBias)[128],
    const float* sCut, const int* sNbr)
{
    const int warp_m = (lw >> 2) & 1, warp_n = lw & 3;
    const int er = lane >> 2, ec2 = (lane & 3) * 2;
    char* atomBase = smem + pid * ATOM_BLK;
    char* dstH = atomBase + ((s == 2) ? IMG_A : 0);
    float* vikT = reinterpret_cast<float*>(smem + W1_OFF + pid * IMG_W);
    const int baG = ba0 + pid;
    const int bA = baG >> 8;
    #pragma unroll
    for (int mt = 0; mt < 2; mt++) {
        #pragma unroll
        for (int nt = 0; nt < 4; nt++) {
            int t = mt*4 + nt;
            int col = warp_n*32 + nt*8 + ec2;
            float b0 = sBias[s][col], b1 = sBias[s][col + 1];
            #pragma unroll
            for (int h = 0; h < 2; h++) {
                int row = warp_m*32 + mt*16 + er + h*8;   // 0..63
                int grow = pid*64 + row;
                __half2 lo2 = *reinterpret_cast<__half2*>(&accL[t][h]);
                float x0 = acc[t][h*2+0] + __half2float(lo2.x) + b0;
                float x1 = acc[t][h*2+1] + __half2float(lo2.y) + b1;
                if (s == 1) {
                    float cu = sCut[grow];
                    const float2 y = *reinterpret_cast<const float2*>(
                        d_y + ((size_t)((bA << 8) + sNbr[grow]) << 7) + col);
                    x0 = x0 * cu * y.x;
                    x1 = x1 * cu * y.y;
                } else if (s == 4) {
                    *reinterpret_cast<float2*>(
                        d_vij + ((size_t)baG * 64 + row) * 128 + col) =
                        make_float2(x0, x1);
                    continue;
                } else if (s == 6) {
                    vikT[col * VPITCH + row]       = x0;
                    vikT[(col + 1) * VPITCH + row] = x1;
                    continue;
                } else {
                    x0 = sspf(x0); x1 = sspf(x1);
                }
                __half2 hp = __floats2half2_rn(x0, x1);
                uint32_t off = (uint32_t)(row * PITCH + col) * 2;
                *reinterpret_cast<uint32_t*>(dstH + off) = *reinterpret_cast<uint32_t*>(&hp);
            }
        }
    }
}

// ---------------- kernel: fused interaction, double-buffered W -------------
__global__ void __launch_bounds__(512, 1) k_main(
    const float* __restrict__ r_ij, const float* __restrict__ cos_ij,
    const float* __restrict__ f_ij, const float* __restrict__ nmask,
    const float* __restrict__ fb1, const float* __restrict__ fb2,
    const float* __restrict__ f2ob,
    const float* __restrict__ aW1, const float* __restrict__ ab1,
    const float* __restrict__ aW2, const float* __restrict__ ab2,
    const float* __restrict__ pb1, const float* __restrict__ pb2,
    const float* __restrict__ eb1, const float* __restrict__ eb2,
    const int* __restrict__ neighbors, float* __restrict__ out_vi)
{
    extern __shared__ char smem[];
    const uint32_t sb = smem_u32(smem);
    const int tid = threadIdx.x;
    const int pid = tid >> 8;            // pipeline/atom: 0 or 1
    const int lt  = tid & 255, lw = lt >> 5, lane = tid & 31;
    const int ba0 = blockIdx.x * 2;

    __shared__ float sCut[128], sMask[128], cmS[384], vsumS[256], hidS[256];
    __shared__ float partS[512];
    __shared__ float sBias[7][128];
    __shared__ int   sNbr[128];
    __shared__ __align__(8) uint64_t mbarW[2];
    const uint32_t mbar0 = smem_u32(&mbarW[0]);
    const uint32_t mbar1 = smem_u32(&mbarW[1]);

    if (tid == 0) {
        asm volatile("mbarrier.init.shared.b64 [%0], %1;" :: "r"(mbar0), "r"(512u) : "memory");
        asm volatile("mbarrier.init.shared.b64 [%0], %1;" :: "r"(mbar1), "r"(512u) : "memory");
    }

    {   // biases to smem
        const float* bp[7] = {fb1, fb2, f2ob, pb1, pb2, eb1, eb2};
        for (int i = tid; i < 7*128; i += 512)
            sBias[i >> 7][i & 127] = __ldg(bp[i >> 7] + (i & 127));
    }
    if (tid < 128) {
        int g = ba0 * NN + tid;
        float r = r_ij[g];
        sCut[tid]  = (r < 5.f) ? 0.5f * (__cosf(r * 0.62831853071795864f) + 1.f) : 0.f;
        float m = nmask[g];
        sMask[tid] = m;
        sNbr[tid]  = neighbors[g];
        cmS[tid*3+0] = cos_ij[(size_t)g*3+0] * m;
        cmS[tid*3+1] = cos_ij[(size_t)g*3+1] * m;
        cmS[tid*3+2] = cos_ij[(size_t)g*3+2] * m;
    }
    {   // zero both atoms' images
        uint64_t* z = reinterpret_cast<uint64_t*>(smem);
        for (int i = tid; i < (2*ATOM_BLK)/8; i += 512) z[i] = 0ull;
    }
    __syncthreads();   // mbar init + zero visible

    {   // issue W(0) -> buf0
        const char* src = reinterpret_cast<const char*>(d_wsplit);
        for (int i = tid * 16; i < WBUF; i += 512*16)
            cp16(smem + W0_OFF + i, src + i);
        asm volatile("cp.async.mbarrier.arrive.noinc.shared.b64 [%0];"
                     :: "r"(mbar0) : "memory");
    }
    {   // scatter features (fp16)
        const float* fg = f_ij + (size_t)(ba0 + pid) * NN * NSB;
        __half* ah = reinterpret_cast<__half*>(smem + pid * ATOM_BLK);
        for (int i = lt; i < NN * NSB; i += 256) {
            int r = i / NSB, c = i - (i / NSB) * NSB;
            ah[r * PITCH + c] = __float2half_rn(fg[i]);
        }
    }
    __syncthreads();   // feature images ready

    float acc[8][4];
    uint32_t accL[8][2];

    for (int s = 0; s < 7; s++) {
        // issue W(s+1) into the other buffer — a full stage of lead
        if (s < 6) {
            const char* src = reinterpret_cast<const char*>(
                d_wsplit + (size_t)(s + 1) * 2 * 128 * PITCH);
            uint32_t woff = ((s + 1) & 1) ? W1_OFF : W0_OFF;
            // stages 3..6 use hi image only
            int nbytes = (s + 1 <= 2) ? WBUF : IMG_W;
            for (int i = tid * 16; i < nbytes; i += 512*16)
                cp16(smem + woff + i, src + i);
            asm volatile("cp.async.mbarrier.arrive.noinc.shared.b64 [%0];"
                         :: "r"(((s + 1) & 1) ? mbar1 : mbar0) : "memory");
        }

        // Q: epilogue of previous stage overlaps P's MMAs
        if (pid == 1 && s > 0) {
            epilogue(s - 1, acc, accL, smem, 1, ba0, lw, lane, sBias, sCut, sNbr);
            asm volatile("bar.sync 2, 256;" ::: "memory");   // Q-internal
        }
        #pragma unroll
        for (int t = 0; t < 8; t++) {
            #pragma unroll
            for (int j = 0; j < 4; j++) acc[t][j] = 0.f;
            accL[t][0] = 0u; accL[t][1] = 0u;
        }

        mbar_wait((s & 1) ? mbar1 : mbar0, (uint32_t)((s >> 1) & 1));

        uint32_t aBase = sb + pid * ATOM_BLK + ((s == 3 || s == 5) ? IMG_A : 0);
        uint32_t wBase = sb + ((s & 1) ? W1_OFF : W0_OFF);
        if (s == 0)      mm<4, true >(aBase, wBase, acc, accL, lw, lane);
        else if (s <= 2) mm<8, true >(aBase, wBase, acc, accL, lw, lane);
        else             mm<8, false>(aBase, wBase, acc, accL, lw, lane);

        // P: epilogue overlaps Q's MMAs
        if (pid == 0 && s < 6)
            epilogue(s, acc, accL, smem, 0, ba0, lw, lane, sBias, sCut, sNbr);

        __syncthreads();
    }

    // stage-6 epilogues (both pipelines) -> vikT in W1 buffer
    epilogue(6, acc, accL, smem, pid, ba0, lw, lane, sBias, sCut, sNbr);
    __syncthreads();

    // ---- Vik[c][d] = sum_n vik[n][c] * cm[n][d] (both atoms) ----
    for (int e = tid; e < 768; e += 512) {
        int atom = e / 384, rem = e - atom * 384;
        int c = rem / 3, d = rem - 3 * (rem / 3);
        const float* vikT = reinterpret_cast<const float*>(smem + W1_OFF + atom * IMG_W);
        float s = 0.f;
        #pragma unroll 8
        for (int n = 0; n < 64; n++)
            s = fmaf(vikT[c * VPITCH + n], cmS[(atom*64 + n) * 3 + d], s);
        d_Vik[(size_t)(ba0 + atom) * 384 + rem] = s;
    }

    // ---- vsum from V (fp16 image) ----
    if (tid < 256) {
        int atom = tid >> 7, c = tid & 127;
        const __half* vh = reinterpret_cast<const __half*>(smem + atom*ATOM_BLK + IMG_A);
        float s = 0.f;
        #pragma unroll 8
        for (int n = 0; n < 64; n++)
            s = fmaf(__half2float(vh[n * PITCH + c]), sMask[atom*64 + n], s);
        vsumS[tid] = s;
    }
    __syncthreads();

    // ---- atom MLP layer 1: 512-thread split-k partials ----
    {
        int atom = tid >> 8, half = (tid >> 7) & 1, c = tid & 127;
        const float* vs = vsumS + atom * 128 + half * 64;
        const float* w  = aW1 + (half * 64) * 128 + c;
        float h = 0.f;
        #pragma unroll 8
        for (int k = 0; k < 64; k++)
            h = fmaf(vs[k], __ldg(w + k * 128), h);
        partS[tid] = h;
    }
    __syncthreads();
    if (tid < 256) {
        int atom = tid >> 7, c = tid & 127;
        hidS[tid] = sspf(partS[atom*256 + c] + partS[atom*256 + 128 + c] + __ldg(ab1 + c));
    }
    __syncthreads();

    // ---- atom MLP layer 2: 512-thread split-k partials ----
    {
        int atom = tid >> 8, half = (tid >> 7) & 1, c = tid & 127;
        const float* hs = hidS + atom * 128 + half * 64;
        const float* w  = aW2 + (half * 64) * 128 + c;
        float o = 0.f;
        #pragma unroll 8
        for (int k = 0; k < 64; k++)
            o = fmaf(hs[k], __ldg(w + k * 128), o);
        partS[tid] = o;
    }
    __syncthreads();
    if (tid < 256) {
        int atom = tid >> 7, c = tid & 127;
        out_vi[(size_t)(ba0 + atom) * NF + c] =
            partS[atom*256 + c] + partS[atom*256 + 128 + c] + __ldg(ab2 + c);
    }
}

// ---------------- kernel: assemble V (warp per idx, 12 floats/lane) --------
__global__ void __launch_bounds__(256) k_assemble(
    const float* __restrict__ cos_ij,
    const int* __restrict__ neighbors,
    float* __restrict__ outV) {
    int idx  = blockIdx.x * 8 + (threadIdx.x >> 5);   // (b,a,n) flat
    int lane = threadIdx.x & 31;
    int ba   = idx >> 6;
    int b    = idx >> 14;
    int nb   = __ldg(neighbors + idx);
    int e0   = lane * 12;

    const float* vikL = d_Vik + (size_t)ba * 384 + e0;
    const float* vikN = d_Vik + ((size_t)(b * AA + nb)) * 384 + e0;
    float4 l0 = *reinterpret_cast<const float4*>(vikL);
    float4 l1 = *reinterpret_cast<const float4*>(vikL + 4);
    float4 l2 = *reinterpret_cast<const float4*>(vikL + 8);
    float4 n0 = *reinterpret_cast<const float4*>(vikN);
    float4 n1 = *reinterpret_cast<const float4*>(vikN + 4);
    float4 n2 = *reinterpret_cast<const float4*>(vikN + 8);
    float4 vij4 = __ldg(reinterpret_cast<const float4*>(d_vij + (size_t)idx * 128) + lane);
    float cc0 = __ldg(cos_ij + (size_t)idx * 3 + 0);
    float cc1 = __ldg(cos_ij + (size_t)idx * 3 + 1);
    float cc2 = __ldg(cos_ij + (size_t)idx * 3 + 2);

    float vs[12] = {l0.x+n0.x, l0.y+n0.y, l0.z+n0.z, l0.w+n0.w,
                    l1.x+n1.x, l1.y+n1.y, l1.z+n1.z, l1.w+n1.w,
                    l2.x+n2.x, l2.y+n2.y, l2.z+n2.z, l2.w+n2.w};
    float vij[4] = {vij4.x, vij4.y, vij4.z, vij4.w};
    float cc[3]  = {cc0, cc1, cc2};
    float o[12];
    #pragma unroll
    for (int j = 0; j < 12; j++) {
        int c = j / 3, d = j - 3 * c;
        o[j] = fmaf(vij[c], cc[d], vs[j]);
    }
    float* dst = outV + (size_t)idx * 384 + e0;
    *reinterpret_cast<float4*>(dst)     = make_float4(o[0], o[1], o[2],  o[3]);
    *reinterpret_cast<float4*>(dst + 4) = make_float4(o[4], o[5], o[6],  o[7]);
    *reinterpret_cast<float4*>(dst + 8) = make_float4(o[8], o[9], o[10], o[11]);
}

// ---------------- launch ----------------
extern "C" void kernel_launch(void* const* d_in, const int* in_sizes, int n_in,
                              void* d_out, int out_size) {
    const float* xi       = (const float*)d_in[0];
    const float* r_ij     = (const float*)d_in[1];
    const float* cos_ij   = (const float*)d_in[2];
    const float* f_ij     = (const float*)d_in[3];
    const float* nmask    = (const float*)d_in[4];
    const float* fW1      = (const float*)d_in[5];
    const float* fb1      = (const float*)d_in[6];
    const float* fW2      = (const float*)d_in[7];
    const float* fb2      = (const float*)d_in[8];
    const float* in2f_W   = (const float*)d_in[9];
    const float* f2oW     = (const float*)d_in[10];
    const float* f2ob     = (const float*)d_in[11];
    const float* aW1      = (const float*)d_in[12];
    const float* ab1      = (const float*)d_in[13];
    const float* aW2      = (const float*)d_in[14];
    const float* ab2      = (const float*)d_in[15];
    const float* pW1      = (const float*)d_in[16];
    const float* pb1      = (const float*)d_in[17];
    const float* pW2      = (const float*)d_in[18];
    const float* pb2      = (const float*)d_in[19];
    const float* eW1      = (const float*)d_in[20];
    const float* eb1      = (const float*)d_in[21];
    const float* eW2      = (const float*)d_in[22];
    const float* eb2      = (const float*)d_in[23];
    const int*   neighbors= (const int*)d_in[24];

    float* out = (float*)d_out;
    float* out_vi = out;                          // [B,A,NCB]
    float* out_V  = out + (size_t)BB*AA*NCB;      // [B,A,N,NCB,3]

    cudaFuncSetAttribute(k_init, cudaFuncAttributeMaxDynamicSharedMemorySize,
                         (int)INIT_SMEM);
    cudaFuncSetAttribute(k_main, cudaFuncAttributeMaxDynamicSharedMemorySize,
                         (int)SMEM_BYTES);

    k_init<<<14 + BB*AA/64, 256, INIT_SMEM>>>(fW1, fW2, f2oW, pW1, pW2, eW1, eW2,
                                              xi, in2f_W);
    k_main<<<BB*AA/2, 512, SMEM_BYTES>>>(
        r_ij, cos_ij, f_ij, nmask,
        fb1, fb2, f2ob, aW1, ab1, aW2, ab2,
        pb1, pb2, eb1, eb2, neighbors, out_vi);
    k_assemble<<<BB*AA*NN/8, 256>>>(cos_ij, neighbors, out_V);
}

// round 17
// speedup vs baseline: 1.8100x; 1.0644x over previous
#include <cuda_runtime.h>
#include <cuda_fp16.h>
#include <stdint.h>

#define BB  4
#define AA  256
#define NN  64
#define NCB 128
#define NF  128
#define NSB 50

#define PITCH 136
#define IMG_A (64 * PITCH * 2)          // 17408
#define IMG_W (128 * PITCH * 2)         // 34816
#define ATOM_BLK (2 * IMG_A)            // 34816 (Ah, Vh per atom)
#define WBUF (2 * IMG_W)                // 69632 (hi + lo)
#define W0_OFF (2 * ATOM_BLK)           // 69632
#define W1_OFF (W0_OFF + WBUF)          // 139264
#define SMEM_BYTES (W1_OFF + WBUF)      // 208896
#define VPITCH 65
#define INIT_SMEM (3 * IMG_A)           // 52224 (Ah64 + Wh64 + Wl64)

// ---------------- global scratch ----------------
__device__ __align__(16) float d_y[BB*AA*NF];
__device__ __align__(16) float d_vij[(size_t)BB*AA*NN*NCB];
__device__ __align__(16) float d_Vik[BB*AA*NCB*3];
__device__ __align__(16) __half d_wsplit[7 * 2 * 128 * PITCH];

// ---------------- helpers ----------------
__device__ __forceinline__ void cp16(void* sdst, const void* gsrc) {
    unsigned s = (unsigned)__cvta_generic_to_shared(sdst);
    asm volatile("cp.async.cg.shared.global [%0], [%1], 16;" :: "r"(s), "l"(gsrc));
}
__device__ __forceinline__ void ldsm4(uint32_t* r, uint32_t saddr) {
    asm volatile("ldmatrix.sync.aligned.m8n8.x4.shared.b16 {%0,%1,%2,%3}, [%4];"
        : "=r"(r[0]), "=r"(r[1]), "=r"(r[2]), "=r"(r[3]) : "r"(saddr));
}
__device__ __forceinline__ void mma16816(float* c, const uint32_t* a,
                                         uint32_t b0, uint32_t b1) {
    asm volatile("mma.sync.aligned.m16n8k16.row.col.f32.f16.f16.f32 "
        "{%0,%1,%2,%3}, {%4,%5,%6,%7}, {%8,%9}, {%0,%1,%2,%3};"
        : "+f"(c[0]), "+f"(c[1]), "+f"(c[2]), "+f"(c[3])
        : "r"(a[0]), "r"(a[1]), "r"(a[2]), "r"(a[3]), "r"(b0), "r"(b1));
}
__device__ __forceinline__ void mma16816h(uint32_t* c, const uint32_t* a,
                                          uint32_t b0, uint32_t b1) {
    asm volatile("mma.sync.aligned.m16n8k16.row.col.f16.f16.f16.f16 "
        "{%0,%1}, {%2,%3,%4,%5}, {%6,%7}, {%0,%1};"
        : "+r"(c[0]), "+r"(c[1])
        : "r"(a[0]), "r"(a[1]), "r"(a[2]), "r"(a[3]), "r"(b0), "r"(b1));
}
__device__ __forceinline__ float sspf(float x) {
    if (x > 15.f) return x - 0.69314718055994531f;
    return __logf(1.f + __expf(x)) - 0.69314718055994531f;
}
__device__ __forceinline__ uint32_t smem_u32(const void* p) {
    return (uint32_t)__cvta_generic_to_shared(p);
}
__device__ __forceinline__ void mbar_wait(uint32_t mb, uint32_t parity) {
    uint32_t done;
    asm volatile("{\n\t.reg .pred p;\n\t"
        "mbarrier.try_wait.parity.acquire.cta.shared::cta.b64 p, [%1], %2;\n\t"
        "selp.b32 %0, 1, 0, p;\n\t}"
        : "=r"(done) : "r"(mb), "r"(parity) : "memory");
    if (!done) {
        asm volatile("{\n\t.reg .pred P1;\n\t"
            "W_%=:\n\t"
            "mbarrier.try_wait.parity.acquire.cta.shared::cta.b64 P1, [%0], %1, 0x989680;\n\t"
            "@P1 bra.uni D_%=;\n\t"
            "bra.uni W_%=;\n\t"
            "D_%=:\n\t}"
            :: "r"(mb), "r"(parity) : "memory");
    }
}

// 2-product (or hi-only) GEMM, m32n32 warp tile, software-pipelined k-loop.
template<int KSTEPS, bool LO>
__device__ __forceinline__ void mm(uint32_t aBase, uint32_t wBase,
                                   float (&acc)[8][4], uint32_t (&accL)[8][2],
                                   int lw, int lane) {
    const int warp_m = (lw >> 2) & 1, warp_n = lw & 3;
    const int rsel = lane & 15, hsel = lane >> 4;
    uint32_t aAddr = aBase + (uint32_t)(((warp_m*32 + rsel) * PITCH + hsel*8) * 2);
    uint32_t wAddr = wBase + (uint32_t)(((warp_n*32 + rsel) * PITCH + hsel*8) * 2);
    const uint32_t STEP16 = 16 * PITCH * 2;

    uint32_t A[2][2][4], Wh[2][2][4], Wl[2][2][4];
    ldsm4(A[0][0],  aAddr);
    ldsm4(A[0][1],  aAddr + STEP16);
    ldsm4(Wh[0][0], wAddr);
    ldsm4(Wh[0][1], wAddr + STEP16);
    if (LO) {
        ldsm4(Wl[0][0], wAddr + IMG_W);
        ldsm4(Wl[0][1], wAddr + IMG_W + STEP16);
    }

    #pragma unroll
    for (int kk = 0; kk < KSTEPS; kk++) {
        const int cur = kk & 1, nxt = cur ^ 1;
        if (kk + 1 < KSTEPS) {
            uint32_t ak = aAddr + (kk + 1) * 32;
            uint32_t wk = wAddr + (kk + 1) * 32;
            ldsm4(A[nxt][0],  ak);
            ldsm4(A[nxt][1],  ak + STEP16);
            ldsm4(Wh[nxt][0], wk);
            ldsm4(Wh[nxt][1], wk + STEP16);
            if (LO) {
                ldsm4(Wl[nxt][0], wk + IMG_W);
                ldsm4(Wl[nxt][1], wk + IMG_W + STEP16);
            }
        }
        #pragma unroll
        for (int mt = 0; mt < 2; mt++)
            #pragma unroll
            for (int q = 0; q < 2; q++)
                #pragma unroll
                for (int j = 0; j < 2; j++) {
                    int t = mt*4 + q*2 + j;
                    mma16816(acc[t],  A[cur][mt], Wh[cur][q][j], Wh[cur][q][j+2]);
                    if (LO)
                        mma16816h(accL[t], A[cur][mt], Wl[cur][q][j], Wl[cur][q][j+2]);
                }
    }
}

// ---------------- kernel: weight prep (blocks 0-27) + HMMA embed (28-59) ---
__global__ void __launch_bounds__(256) k_init(
    const float* fW1, const float* fW2, const float* f2oW,
    const float* pW1, const float* pW2, const float* eW1, const float* eW2,
    const float* __restrict__ xi, const float* __restrict__ in2f_W) {
    extern __shared__ char sdyn[];
    int bid = blockIdx.x;
    int tid = threadIdx.x;
    if (bid < 28) {
        int st = bid >> 2, quarter = bid & 3;
        const float* W; int K, realK;
        switch (st) {
            case 0: W = fW1;  K = 64;  realK = NSB; break;
            case 1: W = fW2;  K = 128; realK = 128; break;
            case 2: W = f2oW; K = 128; realK = 128; break;
            case 3: W = pW1;  K = 128; realK = 128; break;
            case 4: W = pW2;  K = 128; realK = 128; break;
            case 5: W = eW1;  K = 128; realK = 128; break;
            default: W = eW2; K = 128; realK = 128; break;
        }
        int k0 = quarter * 32;
        if (k0 >= K) return;
        __half* hi = d_wsplit + (size_t)st * 2 * 128 * PITCH;
        __half* lo = hi + 128 * PITCH;
        // 128 n x 16 k-pairs
        for (int i = tid; i < 128 * 16; i += 256) {
            int kp = i >> 7, n = i & 127;
            int k = k0 + kp * 2;
            float v0 = (k     < realK) ? W[(size_t)k       * 128 + n] : 0.f;
            float v1 = (k + 1 < realK) ? W[(size_t)(k + 1) * 128 + n] : 0.f;
            __half h0 = __float2half_rn(v0);
            __half h1 = __float2half_rn(v1);
            __half2 hp; hp.x = h0; hp.y = h1;
            __half2 lp = __floats2half2_rn(v0 - __half2float(h0),
                                           v1 - __half2float(h1));
            *reinterpret_cast<__half2*>(hi + (size_t)n * PITCH + k) = hp;
            *reinterpret_cast<__half2*>(lo + (size_t)n * PITCH + k) = lp;
        }
    } else {
        // HMMA embed: block = 64 rows x 64 n-cols; d_y = xi @ in2f_W (fp16 2-prod)
        const int eb = bid - 28;
        const int row0 = (eb >> 1) * 64;
        const int n0   = (eb & 1) * 64;
        __half* Ah = reinterpret_cast<__half*>(sdyn);             // 64 x PITCH
        __half* Wh = reinterpret_cast<__half*>(sdyn + IMG_A);     // 64 x PITCH
        __half* Wl = reinterpret_cast<__half*>(sdyn + 2*IMG_A);
        for (int i = tid; i < 64 * 128; i += 256) {
            int r = i >> 7, c = i & 127;
            Ah[r * PITCH + c] = __float2half_rn(xi[(size_t)(row0 + r) * 128 + c]);
        }
        for (int i = tid; i < 64 * 128; i += 256) {
            int nl = i >> 7, k = i & 127;          // consecutive threads -> consecutive k? no: i&127=k varies fastest -> coalesced over k? stride 128 floats in W... swap:
            (void)nl; (void)k;
            break;
        }
        // W load: [k][n] source; consecutive threads -> consecutive n (coalesced)
        for (int i = tid; i < 128 * 64; i += 256) {
            int k = i >> 6, nl = i & 63;
            float v = __ldg(in2f_W + (size_t)k * 128 + n0 + nl);
            __half h = __float2half_rn(v);
            Wh[nl * PITCH + k] = h;
            Wl[nl * PITCH + k] = __float2half_rn(v - __half2float(h));
        }
        __syncthreads();

        // 8 warps: 4 m-positions (m16) x 2 n-positions (n32)
        const int lw = tid >> 5, lane = tid & 31;
        const int warp_m = lw & 3, warp_n = lw >> 2;
        const int rsel = lane & 15, hsel = lane >> 4;
        uint32_t aA = smem_u32(Ah) + (uint32_t)(((warp_m*16 + rsel) * PITCH + hsel*8) * 2);
        uint32_t wA = smem_u32(Wh) + (uint32_t)(((warp_n*32 + rsel) * PITCH + hsel*8) * 2);
        const uint32_t STEP16 = 16 * PITCH * 2;
        float acc[4][4];
        uint32_t accL[4][2];
        #pragma unroll
        for (int g = 0; g < 4; g++) {
            #pragma unroll
            for (int j = 0; j < 4; j++) acc[g][j] = 0.f;
            accL[g][0] = 0u; accL[g][1] = 0u;
        }
        #pragma unroll 2
        for (int kk = 0; kk < 8; kk++) {
            uint32_t A[4], W0[4], W1[4], L0[4], L1[4];
            uint32_t ko = kk * 32;
            ldsm4(A,  aA + ko);
            ldsm4(W0, wA + ko);
            ldsm4(W1, wA + ko + STEP16);
            ldsm4(L0, wA + ko + IMG_A);
            ldsm4(L1, wA + ko + IMG_A + STEP16);
            mma16816(acc[0], A, W0[0], W0[2]);  mma16816h(accL[0], A, L0[0], L0[2]);
            mma16816(acc[1], A, W0[1], W0[3]);  mma16816h(accL[1], A, L0[1], L0[3]);
            mma16816(acc[2], A, W1[0], W1[2]);  mma16816h(accL[2], A, L1[0], L1[2]);
            mma16816(acc[3], A, W1[1], W1[3]);  mma16816h(accL[3], A, L1[1], L1[3]);
        }
        const int er = lane >> 2, ec2 = (lane & 3) * 2;
        #pragma unroll
        for (int g = 0; g < 4; g++) {
            int col = n0 + warp_n*32 + g*8 + ec2;
            #pragma unroll
            for (int h = 0; h < 2; h++) {
                int row = warp_m*16 + er + h*8;
                __half2 lo2 = *reinterpret_cast<__half2*>(&accL[g][h]);
                float x0 = acc[g][h*2+0] + __half2float(lo2.x);
                float x1 = acc[g][h*2+1] + __half2float(lo2.y);
                *reinterpret_cast<float2*>(
                    d_y + (size_t)(row0 + row) * 128 + col) = make_float2(x0, x1);
            }
        }
    }
}

// stage epilogue for one pipeline (m32n32 tile mapping)
__device__ __forceinline__ void epilogue(
    int s, float (&acc)[8][4], uint32_t (&accL)[8][2], char* smem, int pid, int ba0,
    int lw, int lane, const float (*sBias)[128],
    const float* sCut, const int* sNbr)
{
    const int warp_m = (lw >> 2) & 1, warp_n = lw & 3;
    const int er = lane >> 2, ec2 = (lane & 3) * 2;
    char* atomBase = smem + pid * ATOM_BLK;
    char* dstH = atomBase + ((s == 2) ? IMG_A : 0);
    float* vikT = reinterpret_cast<float*>(smem + W1_OFF + pid * IMG_W);
    const int baG = ba0 + pid;
    const int bA = baG >> 8;
    #pragma unroll
    for (int mt = 0; mt < 2; mt++) {
        #pragma unroll
        for (int nt = 0; nt < 4; nt++) {
            int t = mt*4 + nt;
            int col = warp_n*32 + nt*8 + ec2;
            float b0 = sBias[s][col], b1 = sBias[s][col + 1];
            #pragma unroll
            for (int h = 0; h < 2; h++) {
                int row = warp_m*32 + mt*16 + er + h*8;   // 0..63
                int grow = pid*64 + row;
                __half2 lo2 = *reinterpret_cast<__half2*>(&accL[t][h]);
                float x0 = acc[t][h*2+0] + __half2float(lo2.x) + b0;
                float x1 = acc[t][h*2+1] + __half2float(lo2.y) + b1;
                if (s == 1) {
                    float cu = sCut[grow];
                    const float2 y = *reinterpret_cast<const float2*>(
                        d_y + ((size_t)((bA << 8) + sNbr[grow]) << 7) + col);
                    x0 = x0 * cu * y.x;
                    x1 = x1 * cu * y.y;
                } else if (s == 4) {
                    *reinterpret_cast<float2*>(
                        d_vij + ((size_t)baG * 64 + row) * 128 + col) =
                        make_float2(x0, x1);
                    continue;
                } else if (s == 6) {
                    vikT[col * VPITCH + row]       = x0;
                    vikT[(col + 1) * VPITCH + row] = x1;
                    continue;
                } else {
                    x0 = sspf(x0); x1 = sspf(x1);
                }
                __half2 hp = __floats2half2_rn(x0, x1);
                uint32_t off = (uint32_t)(row * PITCH + col) * 2;
                *reinterpret_cast<uint32_t*>(dstH + off) = *reinterpret_cast<uint32_t*>(&hp);
            }
        }
    }
}

// ---------------- kernel: fused interaction, double-buffered W -------------
__global__ void __launch_bounds__(512, 1) k_main(
    const float* __restrict__ r_ij, const float* __restrict__ cos_ij,
    const float* __restrict__ f_ij, const float* __restrict__ nmask,
    const float* __restrict__ fb1, const float* __restrict__ fb2,
    const float* __restrict__ f2ob,
    const float* __restrict__ aW1, const float* __restrict__ ab1,
    const float* __restrict__ aW2, const float* __restrict__ ab2,
    const float* __restrict__ pb1, const float* __restrict__ pb2,
    const float* __restrict__ eb1, const float* __restrict__ eb2,
    const int* __restrict__ neighbors, float* __restrict__ out_vi)
{
    extern __shared__ char smem[];
    const uint32_t sb = smem_u32(smem);
    const int tid = threadIdx.x;
    const int pid = tid >> 8;            // pipeline/atom: 0 or 1
    const int lt  = tid & 255, lw = lt >> 5, lane = tid & 31;
    const int ba0 = blockIdx.x * 2;

    __shared__ float sCut[128], sMask[128], cmS[384], vsumS[256], hidS[256];
    __shared__ float partS[512];
    __shared__ float sBias[7][128];
    __shared__ int   sNbr[128];
    __shared__ __align__(8) uint64_t mbarW[2];
    const uint32_t mbar0 = smem_u32(&mbarW[0]);
    const uint32_t mbar1 = smem_u32(&mbarW[1]);

    if (tid == 0) {
        asm volatile("mbarrier.init.shared.b64 [%0], %1;" :: "r"(mbar0), "r"(512u) : "memory");
        asm volatile("mbarrier.init.shared.b64 [%0], %1;" :: "r"(mbar1), "r"(512u) : "memory");
    }

    {   // biases to smem
        const float* bp[7] = {fb1, fb2, f2ob, pb1, pb2, eb1, eb2};
        for (int i = tid; i < 7*128; i += 512)
            sBias[i >> 7][i & 127] = __ldg(bp[i >> 7] + (i & 127));
    }
    if (tid < 128) {
        int g = ba0 * NN + tid;
        float r = r_ij[g];
        sCut[tid]  = (r < 5.f) ? 0.5f * (__cosf(r * 0.62831853071795864f) + 1.f) : 0.f;
        float m = nmask[g];
        sMask[tid] = m;
        sNbr[tid]  = neighbors[g];
        cmS[tid*3+0] = cos_ij[(size_t)g*3+0] * m;
        cmS[tid*3+1] = cos_ij[(size_t)g*3+1] * m;
        cmS[tid*3+2] = cos_ij[(size_t)g*3+2] * m;
    }
    {   // zero both atoms' images
        uint64_t* z = reinterpret_cast<uint64_t*>(smem);
        for (int i = tid; i < (2*ATOM_BLK)/8; i += 512) z[i] = 0ull;
    }
    __syncthreads();   // mbar init + zero visible

    {   // issue W(0) -> buf0 (hi + lo)
        const char* src = reinterpret_cast<const char*>(d_wsplit);
        for (int i = tid * 16; i < WBUF; i += 512*16)
            cp16(smem + W0_OFF + i, src + i);
        asm volatile("cp.async.mbarrier.arrive.noinc.shared.b64 [%0];"
                     :: "r"(mbar0) : "memory");
    }
    {   // scatter features (fp16)
        const float* fg = f_ij + (size_t)(ba0 + pid) * NN * NSB;
        __half* ah = reinterpret_cast<__half*>(smem + pid * ATOM_BLK);
        for (int i = lt; i < NN * NSB; i += 256) {
            int r = i / NSB, c = i - (i / NSB) * NSB;
            ah[r * PITCH + c] = __float2half_rn(fg[i]);
        }
    }
    __syncthreads();   // feature images ready

    float acc[8][4];
    uint32_t accL[8][2];

    for (int s = 0; s < 7; s++) {
        // issue W(s+1) into the other buffer — hi image only (stages >=1)
        if (s < 6) {
            const char* src = reinterpret_cast<const char*>(
                d_wsplit + (size_t)(s + 1) * 2 * 128 * PITCH);
            uint32_t woff = ((s + 1) & 1) ? W1_OFF : W0_OFF;
            for (int i = tid * 16; i < IMG_W; i += 512*16)
                cp16(smem + woff + i, src + i);
            asm volatile("cp.async.mbarrier.arrive.noinc.shared.b64 [%0];"
                         :: "r"(((s + 1) & 1) ? mbar1 : mbar0) : "memory");
        }

        // Q: epilogue of previous stage overlaps P's MMAs
        if (pid == 1 && s > 0) {
            epilogue(s - 1, acc, accL, smem, 1, ba0, lw, lane, sBias, sCut, sNbr);
            asm volatile("bar.sync 2, 256;" ::: "memory");   // Q-internal
        }
        #pragma unroll
        for (int t = 0; t < 8; t++) {
            #pragma unroll
            for (int j = 0; j < 4; j++) acc[t][j] = 0.f;
            accL[t][0] = 0u; accL[t][1] = 0u;
        }

        mbar_wait((s & 1) ? mbar1 : mbar0, (uint32_t)((s >> 1) & 1));

        uint32_t aBase = sb + pid * ATOM_BLK + ((s == 3 || s == 5) ? IMG_A : 0);
        uint32_t wBase = sb + ((s & 1) ? W1_OFF : W0_OFF);
        if (s == 0) mm<4, true >(aBase, wBase, acc, accL, lw, lane);
        else        mm<8, false>(aBase, wBase, acc, accL, lw, lane);

        // P: epilogue overlaps Q's MMAs
        if (pid == 0 && s < 6)
            epilogue(s, acc, accL, smem, 0, ba0, lw, lane, sBias, sCut, sNbr);

        __syncthreads();
    }

    // stage-6 epilogues (both pipelines) -> vikT in W1 buffer
    epilogue(6, acc, accL, smem, pid, ba0, lw, lane, sBias, sCut, sNbr);
    __syncthreads();

    // ---- Vik[c][d] = sum_n vik[n][c] * cm[n][d] (both atoms) ----
    for (int e = tid; e < 768; e += 512) {
        int atom = e / 384, rem = e - atom * 384;
        int c = rem / 3, d = rem - 3 * (rem / 3);
        const float* vikT = reinterpret_cast<const float*>(smem + W1_OFF + atom * IMG_W);
        float s = 0.f;
        #pragma unroll 8
        for (int n = 0; n < 64; n++)
            s = fmaf(vikT[c * VPITCH + n], cmS[(atom*64 + n) * 3 + d], s);
        d_Vik[(size_t)(ba0 + atom) * 384 + rem] = s;
    }

    // ---- vsum from V (fp16 image) ----
    if (tid < 256) {
        int atom = tid >> 7, c = tid & 127;
        const __half* vh = reinterpret_cast<const __half*>(smem + atom*ATOM_BLK + IMG_A);
        float s = 0.f;
        #pragma unroll 8
        for (int n = 0; n < 64; n++)
            s = fmaf(__half2float(vh[n * PITCH + c]), sMask[atom*64 + n], s);
        vsumS[tid] = s;
    }
    __syncthreads();

    // ---- atom MLP layer 1: 512-thread split-k partials ----
    {
        int atom = tid >> 8, half = (tid >> 7) & 1, c = tid & 127;
        const float* vs = vsumS + atom * 128 + half * 64;
        const float* w  = aW1 + (half * 64) * 128 + c;
        float h = 0.f;
        #pragma unroll 8
        for (int k = 0; k < 64; k++)
            h = fmaf(vs[k], __ldg(w + k * 128), h);
        partS[tid] = h;
    }
    __syncthreads();
    if (tid < 256) {
        int atom = tid >> 7, c = tid & 127;
        hidS[tid] = sspf(partS[atom*256 + c] + partS[atom*256 + 128 + c] + __ldg(ab1 + c));
    }
    __syncthreads();

    // ---- atom MLP layer 2: 512-thread split-k partials ----
    {
        int atom = tid >> 8, half = (tid >> 7) & 1, c = tid & 127;
        const float* hs = hidS + atom * 128 + half * 64;
        const float* w  = aW2 + (half * 64) * 128 + c;
        float o = 0.f;
        #pragma unroll 8
        for (int k = 0; k < 64; k++)
            o = fmaf(hs[k], __ldg(w + k * 128), o);
        partS[tid] = o;
    }
    __syncthreads();
    if (tid < 256) {
        int atom = tid >> 7, c = tid & 127;
        out_vi[(size_t)(ba0 + atom) * NF + c] =
            partS[atom*256 + c] + partS[atom*256 + 128 + c] + __ldg(ab2 + c);
    }
}

// ---------------- kernel: assemble V (warp per idx, 12 floats/lane) --------
__global__ void __launch_bounds__(256) k_assemble(
    const float* __restrict__ cos_ij,
    const int* __restrict__ neighbors,
    float* __restrict__ outV) {
    int idx  = blockIdx.x * 8 + (threadIdx.x >> 5);   // (b,a,n) flat
    int lane = threadIdx.x & 31;
    int ba   = idx >> 6;
    int b    = idx >> 14;
    int nb   = __ldg(neighbors + idx);
    int e0   = lane * 12;

    const float* vikL = d_Vik + (size_t)ba * 384 + e0;
    const float* vikN = d_Vik + ((size_t)(b * AA + nb)) * 384 + e0;
    float4 l0 = *reinterpret_cast<const float4*>(vikL);
    float4 l1 = *reinterpret_cast<const float4*>(vikL + 4);
    float4 l2 = *reinterpret_cast<const float4*>(vikL + 8);
    float4 n0 = *reinterpret_cast<const float4*>(vikN);
    float4 n1 = *reinterpret_cast<const float4*>(vikN + 4);
    float4 n2 = *reinterpret_cast<const float4*>(vikN + 8);
    float4 vij4 = __ldg(reinterpret_cast<const float4*>(d_vij + (size_t)idx * 128) + lane);
    float cc0 = __ldg(cos_ij + (size_t)idx * 3 + 0);
    float cc1 = __ldg(cos_ij + (size_t)idx * 3 + 1);
    float cc2 = __ldg(cos_ij + (size_t)idx * 3 + 2);

    float vs[12] = {l0.x+n0.x, l0.y+n0.y, l0.z+n0.z, l0.w+n0.w,
                    l1.x+n1.x, l1.y+n1.y, l1.z+n1.z, l1.w+n1.w,
                    l2.x+n2.x, l2.y+n2.y, l2.z+n2.z, l2.w+n2.w};
    float vij[4] = {vij4.x, vij4.y, vij4.z, vij4.w};
    float cc[3]  = {cc0, cc1, cc2};
    float o[12];
    #pragma unroll
    for (int j = 0; j < 12; j++) {
        int c = j / 3, d = j - 3 * c;
        o[j] = fmaf(vij[c], cc[d], vs[j]);
    }
    float* dst = outV + (size_t)idx * 384 + e0;
    *reinterpret_cast<float4*>(dst)     = make_float4(o[0], o[1], o[2],  o[3]);
    *reinterpret_cast<float4*>(dst + 4) = make_float4(o[4], o[5], o[6],  o[7]);
    *reinterpret_cast<float4*>(dst + 8) = make_float4(o[8], o[9], o[10], o[11]);
}

// ---------------- launch ----------------
extern "C" void kernel_launch(void* const* d_in, const int* in_sizes, int n_in,
                              void* d_out, int out_size) {
    const float* xi       = (const float*)d_in[0];
    const float* r_ij     = (const float*)d_in[1];
    const float* cos_ij   = (const float*)d_in[2];
    const float* f_ij     = (const float*)d_in[3];
    const float* nmask    = (const float*)d_in[4];
    const float* fW1      = (const float*)d_in[5];
    const float* fb1      = (const float*)d_in[6];
    const float* fW2      = (const float*)d_in[7];
    const float* fb2      = (const float*)d_in[8];
    const float* in2f_W   = (const float*)d_in[9];
    const float* f2oW     = (const float*)d_in[10];
    const float* f2ob     = (const float*)d_in[11];
    const float* aW1      = (const float*)d_in[12];
    const float* ab1      = (const float*)d_in[13];
    const float* aW2      = (const float*)d_in[14];
    const float* ab2      = (const float*)d_in[15];
    const float* pW1      = (const float*)d_in[16];
    const float* pb1      = (const float*)d_in[17];
    const float* pW2      = (const float*)d_in[18];
    const float* pb2      = (const float*)d_in[19];
    const float* eW1      = (const float*)d_in[20];
    const float* eb1      = (const float*)d_in[21];
    const float* eW2      = (const float*)d_in[22];
    const float* eb2      = (const float*)d_in[23];
    const int*   neighbors= (const int*)d_in[24];

    float* out = (float*)d_out;
    float* out_vi = out;                          // [B,A,NCB]
    float* out_V  = out + (size_t)BB*AA*NCB;      // [B,A,N,NCB,3]

    cudaFuncSetAttribute(k_init, cudaFuncAttributeMaxDynamicSharedMemorySize,
                         (int)INIT_SMEM);
    cudaFuncSetAttribute(k_main, cudaFuncAttributeMaxDynamicSharedMemorySize,
                         (int)SMEM_BYTES);

    k_init<<<28 + BB*AA/32, 256, INIT_SMEM>>>(fW1, fW2, f2oW, pW1, pW2, eW1, eW2,
                                              xi, in2f_W);
    k_main<<<BB*AA/2, 512, SMEM_BYTES>>>(
        r_ij, cos_ij, f_ij, nmask,
        fb1, fb2, f2ob, aW1, ab1, aW2, ab2,
        pb1, pb2, eb1, eb2, neighbors, out_vi);
    k_assemble<<<BB*AA*NN/8, 256>>>(cos_ij, neighbors, out_V);
}